// round 5
// baseline (speedup 1.0000x reference)
#include <cuda_runtime.h>
#include <cstdint>
#include <math.h>

#define T_SEQ 2048
#define NH 16
#define HD 64
#define CEMB 1024
#define KVW 512

// ---------------- scratch (device globals) ----------------------------------
static __device__ float g_qraw[T_SEQ * CEMB];
static __device__ float g_kraw[T_SEQ * CEMB];
static __device__ float g_vraw[T_SEQ * CEMB];
static __device__ float g_qn[NH * T_SEQ * HD];
static __device__ float g_kn[NH * T_SEQ * HD];
static __device__ float g_kv[NH * T_SEQ * KVW];   // [h][t][n], tf32-rounded
static __device__ float g_y[T_SEQ * CEMB];

// ---------------- helpers ----------------------------------------------------
static __device__ __forceinline__ float tf32r(float x) {
    float y; asm("cvt.rna.tf32.f32 %0, %1;" : "=f"(y) : "f"(x)); return y;
}
static __device__ __forceinline__ void mma_tf32(
    float* acc, uint32_t a0, uint32_t a1, uint32_t a2, uint32_t a3,
    uint32_t b0, uint32_t b1)
{
    asm volatile(
        "mma.sync.aligned.m16n8k8.row.col.f32.tf32.tf32.f32 "
        "{%0,%1,%2,%3},{%4,%5,%6,%7},{%8,%9},{%0,%1,%2,%3};"
        : "+f"(acc[0]), "+f"(acc[1]), "+f"(acc[2]), "+f"(acc[3])
        : "r"(a0), "r"(a1), "r"(a2), "r"(a3), "r"(b0), "r"(b1));
}
static __device__ __forceinline__ void mma_bf16(
    float* acc, uint32_t a0, uint32_t a1, uint32_t a2, uint32_t a3,
    uint32_t b0, uint32_t b1)
{
    asm volatile(
        "mma.sync.aligned.m16n8k16.row.col.f32.bf16.bf16.f32 "
        "{%0,%1,%2,%3},{%4,%5,%6,%7},{%8,%9},{%0,%1,%2,%3};"
        : "+f"(acc[0]), "+f"(acc[1]), "+f"(acc[2]), "+f"(acc[3])
        : "r"(a0), "r"(a1), "r"(a2), "r"(a3), "r"(b0), "r"(b1));
}
static __device__ __forceinline__ uint2 pack_split(float f0, float f1) {
    uint32_t h;
    asm("cvt.rn.bf16x2.f32 %0, %1, %2;" : "=r"(h) : "f"(f1), "f"(f0));
    float h0 = __uint_as_float(h << 16);
    float h1 = __uint_as_float(h & 0xffff0000u);
    uint32_t l;
    float r0 = f0 - h0, r1 = f1 - h1;
    asm("cvt.rn.bf16x2.f32 %0, %1, %2;" : "=r"(l) : "f"(r1), "f"(r0));
    return make_uint2(h, l);
}

// ================= bf16 3x-split GEMM body (NT) ===============================
#define BSTR 12
#define BTILE_U (128 * BSTR)

static __device__ __forceinline__ void bf16_nt_body(
    const float* __restrict__ A, const float* __restrict__ B, float* __restrict__ C,
    int K, int lda, int ldb, int ldc, int m0, int n0)
{
    extern __shared__ uint32_t smu[];
    const int STAGE = 4 * BTILE_U;
    int nch = K >> 4;

    int tid = threadIdx.x;
    int lane = tid & 31, wid = tid >> 5;
    int gid = lane >> 2, tig = lane & 3;
    int warp_m = wid & 3, warp_n = wid >> 2;
    int arow = tid >> 1, akc = (tid & 1) * 8;

    float acc[2][8][4];
#pragma unroll
    for (int i = 0; i < 2; i++)
#pragma unroll
        for (int j = 0; j < 8; j++)
#pragma unroll
            for (int q = 0; q < 4; q++) acc[i][j][q] = 0.f;

    float4 ra0, ra1, rb0, rb1;
    auto LOADG = [&](int k0) {
        const float* ap = A + (long)(m0 + arow) * lda + k0 + akc;
        ra0 = *(const float4*)ap;
        ra1 = *(const float4*)(ap + 4);
        const float* bp = B + (long)(n0 + arow) * ldb + k0 + akc;
        rb0 = *(const float4*)bp;
        rb1 = *(const float4*)(bp + 4);
    };
    auto STORES = [&](int sb) {
        int ao = arow * BSTR + (akc >> 1);
        uint2 p0 = pack_split(ra0.x, ra0.y), p1 = pack_split(ra0.z, ra0.w);
        uint2 p2 = pack_split(ra1.x, ra1.y), p3 = pack_split(ra1.z, ra1.w);
        *(uint4*)(smu + sb + ao)               = make_uint4(p0.x, p1.x, p2.x, p3.x);
        *(uint4*)(smu + sb + 2 * BTILE_U + ao) = make_uint4(p0.y, p1.y, p2.y, p3.y);
        uint2 q0 = pack_split(rb0.x, rb0.y), q1 = pack_split(rb0.z, rb0.w);
        uint2 q2 = pack_split(rb1.x, rb1.y), q3 = pack_split(rb1.z, rb1.w);
        *(uint4*)(smu + sb + BTILE_U + ao)     = make_uint4(q0.x, q1.x, q2.x, q3.x);
        *(uint4*)(smu + sb + 3 * BTILE_U + ao) = make_uint4(q0.y, q1.y, q2.y, q3.y);
    };

    LOADG(0);
    STORES(0);
    __syncthreads();

    for (int ch = 0; ch < nch; ch++) {
        if (ch + 1 < nch) LOADG((ch + 1) << 4);
        int sb = (ch & 1) * STAGE;
#pragma unroll
        for (int p = 0; p < 3; p++) {
            const uint32_t* Abase = smu + sb + (p == 2 ? 2 * BTILE_U : 0);
            const uint32_t* Bbase = smu + sb + BTILE_U + (p == 1 ? 2 * BTILE_U : 0);
            uint32_t af[2][4];
#pragma unroll
            for (int mt = 0; mt < 2; mt++) {
                int r = (warp_m * 32 + mt * 16 + gid) * BSTR + tig;
                af[mt][0] = Abase[r];
                af[mt][1] = Abase[r + 8 * BSTR];
                af[mt][2] = Abase[r + 4];
                af[mt][3] = Abase[r + 8 * BSTR + 4];
            }
            uint32_t bfr[8][2];
#pragma unroll
            for (int nt = 0; nt < 8; nt++) {
                int c = (warp_n * 64 + nt * 8 + gid) * BSTR + tig;
                bfr[nt][0] = Bbase[c];
                bfr[nt][1] = Bbase[c + 4];
            }
#pragma unroll
            for (int mt = 0; mt < 2; mt++)
#pragma unroll
                for (int nt = 0; nt < 8; nt++)
                    mma_bf16(acc[mt][nt], af[mt][0], af[mt][1], af[mt][2],
                             af[mt][3], bfr[nt][0], bfr[nt][1]);
        }
        if (ch + 1 < nch) {
            __syncthreads();
            STORES(((ch + 1) & 1) * STAGE);
            __syncthreads();
        }
    }

#pragma unroll
    for (int mt = 0; mt < 2; mt++) {
        int r0 = m0 + warp_m * 32 + mt * 16 + gid;
#pragma unroll
        for (int nt = 0; nt < 8; nt++) {
            int c = n0 + warp_n * 64 + nt * 8 + tig * 2;
            *(float2*)(C + (long)r0 * ldc + c) =
                make_float2(acc[mt][nt][0], acc[mt][nt][1]);
            *(float2*)(C + (long)(r0 + 8) * ldc + c) =
                make_float2(acc[mt][nt][2], acc[mt][nt][3]);
        }
    }
}

// merged QKV projection: blockIdx.z selects {Wq,Wk,Wv} -> {qraw,kraw,vraw}
__global__ void __launch_bounds__(256, 2) qkv_gemm(
    const float* __restrict__ x,
    const float* __restrict__ Wq, const float* __restrict__ Wk,
    const float* __restrict__ Wv,
    float* q, float* k, float* v)
{
    const float* B = blockIdx.z == 0 ? Wq : blockIdx.z == 1 ? Wk : Wv;
    float* C = blockIdx.z == 0 ? q : blockIdx.z == 1 ? k : v;
    bf16_nt_body(x, B, C, CEMB, CEMB, CEMB, CEMB,
                 blockIdx.y * 128, blockIdx.x * 128);
}

__global__ void __launch_bounds__(256, 2) wo_gemm(
    const float* __restrict__ y, const float* __restrict__ Wo, float* out)
{
    bf16_nt_body(y, Wo, out, CEMB, CEMB, CEMB, CEMB,
                 blockIdx.y * 128, blockIdx.x * 128);
}

// ---------------- rotary + RMS norm + octet norm + KV outer product ---------
__global__ __launch_bounds__(64) void prep_kernel(
    const float* __restrict__ qraw, const float* __restrict__ kraw,
    const float* __restrict__ vraw,
    const float* __restrict__ cosp, const float* __restrict__ sinp,
    float* __restrict__ qn, float* __restrict__ kn, float* __restrict__ kv)
{
    int h = blockIdx.x, t = blockIdx.y, d = threadIdx.x;
    __shared__ float r1[64], r2[64], skc[64], sv[64];

    long base = (long)t * CEMB + h * HD;
    int j = d & 31;
    float c = cosp[t * 32 + j], s = sinp[t * 32 + j];

    float x1q = qraw[base + j], x2q = qraw[base + j + 32];
    float qv = (d < 32) ? (x1q * c + x2q * s) : (x2q * c - x1q * s);
    float x1k = kraw[base + j], x2k = kraw[base + j + 32];
    float kvv = (d < 32) ? (x1k * c + x2k * s) : (x2k * c - x1k * s);

    r1[d] = qv * qv;
    r2[d] = kvv * kvv;
    __syncthreads();
#pragma unroll
    for (int off = 32; off > 0; off >>= 1) {
        if (d < off) { r1[d] += r1[d + off]; r2[d] += r2[d + off]; }
        __syncthreads();
    }
    float rq = rsqrtf(r1[0] * (1.f / 64.f) + 1e-6f);
    float rk = rsqrtf(r2[0] * (1.f / 64.f) + 1e-6f);
    float qno = qv * rq, kno = kvv * rk;

    long nbase = ((long)h * T_SEQ + t) * HD + d;
    qn[nbase] = qno;
    kn[nbase] = kno;

    float o = kno * kno;
    o += __shfl_xor_sync(0xffffffffu, o, 1);
    o += __shfl_xor_sync(0xffffffffu, o, 2);
    o += __shfl_xor_sync(0xffffffffu, o, 4);
    float ko = kno / fmaxf(sqrtf(o), 1e-12f);
    skc[d] = ((d & 7) == 0) ? ko : -ko;
    sv[d] = vraw[base + d];
    __syncthreads();

    // KV pre-rounded to tf32 for the fused Z mma
    float kc = skc[d];
    int mb = d & ~7;
    float* row = kv + ((long)h * T_SEQ + t) * KVW + d * 8;
    float4 a = make_float4(tf32r(kc * sv[mb + 0]), tf32r(kc * sv[mb + 1]),
                           tf32r(kc * sv[mb + 2]), tf32r(kc * sv[mb + 3]));
    float4 b = make_float4(tf32r(kc * sv[mb + 4]), tf32r(kc * sv[mb + 5]),
                           tf32r(kc * sv[mb + 6]), tf32r(kc * sv[mb + 7]));
    *(float4*)row = a;
    *(float4*)(row + 4) = b;
}

// ---------------- octonion math ----------------------------------------------
__device__ __forceinline__ void qmul4(const float* q1, const float* q2, float* r)
{
    r[0] = q1[0]*q2[0] - q1[1]*q2[1] - q1[2]*q2[2] - q1[3]*q2[3];
    r[1] = q1[0]*q2[1] + q1[1]*q2[0] + q1[2]*q2[3] - q1[3]*q2[2];
    r[2] = q1[0]*q2[2] - q1[1]*q2[3] + q1[2]*q2[0] + q1[3]*q2[1];
    r[3] = q1[0]*q2[3] + q1[1]*q2[2] - q1[2]*q2[1] + q1[3]*q2[0];
}
__device__ __forceinline__ void omul8(const float* o1, const float* o2, float* r)
{
    const float* a = o1; const float* b = o1 + 4;
    const float* c = o2; const float* d = o2 + 4;
    float dc[4] = { d[0], -d[1], -d[2], -d[3] };
    float cc[4] = { c[0], -c[1], -c[2], -c[3] };
    float t1[4], t2[4];
    qmul4(a, c, t1); qmul4(dc, b, t2);
    r[0] = t1[0] - t2[0]; r[1] = t1[1] - t2[1];
    r[2] = t1[2] - t2[2]; r[3] = t1[3] - t2[3];
    qmul4(d, a, t1); qmul4(b, cc, t2);
    r[4] = t1[0] + t2[0]; r[5] = t1[1] + t2[1];
    r[6] = t1[2] + t2[2]; r[7] = t1[3] + t2[3];
}

// ================= fused attention =============================================
// One CTA = (head, 64 query rows). Streams 64-key tiles:
//   scores (3x bf16 split) -> exp (no max needed: |score|<=8) -> p~ smem (tf32)
//   Z[64,512] += p~ @ KV  (1x tf32 mma, acc in registers)
//   S[row] += sum p~
// Epilogue: y = octonion(q, Z) / S written directly.
// smem floats: KV 64x520 | P 64x68 | Qhi/Qlo 64x36 u32 | Khi/Klo | S 256
#define OFF_KV 0
#define OFF_P  33280
#define OFF_QH 37632
#define OFF_QL 39936
#define OFF_KH 42240
#define OFF_KL 44544
#define OFF_S  46848
#define FA_SMEM ((OFF_S + 256) * 4)

static __device__ __forceinline__ void load_bf16_tile64(
    const float* __restrict__ src_base, uint32_t* dst_hi, uint32_t* dst_lo, int tid)
{
    int row = tid >> 2, c0 = (tid & 3) * 16;
    const float* s = src_base + (long)row * HD + c0;
    float4 v0 = ((const float4*)s)[0];
    float4 v1 = ((const float4*)s)[1];
    float4 v2 = ((const float4*)s)[2];
    float4 v3 = ((const float4*)s)[3];
    uint2 p0 = pack_split(v0.x, v0.y), p1 = pack_split(v0.z, v0.w);
    uint2 p2 = pack_split(v1.x, v1.y), p3 = pack_split(v1.z, v1.w);
    uint2 p4 = pack_split(v2.x, v2.y), p5 = pack_split(v2.z, v2.w);
    uint2 p6 = pack_split(v3.x, v3.y), p7 = pack_split(v3.z, v3.w);
    int o = row * 36 + (c0 >> 1);
    *(uint4*)(dst_hi + o)     = make_uint4(p0.x, p1.x, p2.x, p3.x);
    *(uint4*)(dst_hi + o + 4) = make_uint4(p4.x, p5.x, p6.x, p7.x);
    *(uint4*)(dst_lo + o)     = make_uint4(p0.y, p1.y, p2.y, p3.y);
    *(uint4*)(dst_lo + o + 4) = make_uint4(p4.y, p5.y, p6.y, p7.y);
}

__global__ void __launch_bounds__(256, 1) fused_attn(
    const float* __restrict__ qn, const float* __restrict__ kn,
    const float* __restrict__ kv, float* __restrict__ y)
{
    extern __shared__ __align__(16) float fsm[];
    uint32_t* usm = (uint32_t*)fsm;

    int rt = 31 - blockIdx.x;          // big tiles launch first
    int h = blockIdx.y;
    int r0 = rt * 64;
    int tid = threadIdx.x, lane = tid & 31, wid = tid >> 5;
    int gid = lane >> 2, tig = lane & 3;

    const float* qh  = qn + ((long)h * T_SEQ + r0) * HD;
    const float* kh  = kn + (long)h * T_SEQ * HD;
    const float* kvh = kv + (long)h * T_SEQ * KVW;

    load_bf16_tile64(qh, usm + OFF_QH, usm + OFF_QL, tid);

    float zacc[2][16][4];
#pragma unroll
    for (int i = 0; i < 2; i++)
#pragma unroll
        for (int j = 0; j < 16; j++)
#pragma unroll
            for (int q = 0; q < 4; q++) zacc[i][j][q] = 0.f;
    float s_acc = 0.f;

    int wms = wid & 3, wns = wid >> 2;   // scores: rows wms*16, cols wns*32
    int wmz = wid & 1, wnz = wid >> 1;   // Z: rows wmz*32, cols wnz*128

    int njt = rt + 1;
    for (int jt = 0; jt < njt; jt++) {
        int j0 = jt * 64;
        __syncthreads();
        // load k tile (bf16 split) + KV tile (raw tf32-rounded f32)
        load_bf16_tile64(kh + (long)j0 * HD, usm + OFF_KH, usm + OFF_KL, tid);
        {
            int row = tid >> 2, c0 = (tid & 3) * 128;
            const float4* src = (const float4*)(kvh + (long)(j0 + row) * KVW + c0);
            float4* dst = (float4*)(fsm + OFF_KV + row * 520 + c0);
#pragma unroll 8
            for (int i = 0; i < 32; i++) dst[i] = src[i];
        }
        __syncthreads();

        // ---- scores: s = q @ k^T (3x bf16 split) ----
        float sacc[4][4];
#pragma unroll
        for (int nt = 0; nt < 4; nt++)
#pragma unroll
            for (int q = 0; q < 4; q++) sacc[nt][q] = 0.f;
#pragma unroll
        for (int ks = 0; ks < 4; ks++) {
#pragma unroll
            for (int p = 0; p < 3; p++) {
                const uint32_t* Ab = usm + (p == 2 ? OFF_QL : OFF_QH);
                const uint32_t* Bb = usm + (p == 1 ? OFF_KL : OFF_KH);
                int ra = (wms * 16 + gid) * 36 + ks * 8 + tig;
                uint32_t a0 = Ab[ra], a1 = Ab[ra + 8 * 36];
                uint32_t a2 = Ab[ra + 4], a3 = Ab[ra + 8 * 36 + 4];
#pragma unroll
                for (int nt = 0; nt < 4; nt++) {
                    int rb = (wns * 32 + nt * 8 + gid) * 36 + ks * 8 + tig;
                    mma_bf16(sacc[nt], a0, a1, a2, a3, Bb[rb], Bb[rb + 4]);
                }
            }
        }
        // ---- exp + causal mask + store p~ (tf32) ----
        bool diag = (jt == rt);
        int rowa = wms * 16 + gid;
#pragma unroll
        for (int nt = 0; nt < 4; nt++) {
            int col = wns * 32 + nt * 8 + tig * 2;
            float p00 = __expf(sacc[nt][0] * 0.125f);
            float p01 = __expf(sacc[nt][1] * 0.125f);
            float p10 = __expf(sacc[nt][2] * 0.125f);
            float p11 = __expf(sacc[nt][3] * 0.125f);
            if (diag) {
                if (col     > rowa)     p00 = 0.f;
                if (col + 1 > rowa)     p01 = 0.f;
                if (col     > rowa + 8) p10 = 0.f;
                if (col + 1 > rowa + 8) p11 = 0.f;
            }
            *(float2*)(fsm + OFF_P + rowa * 68 + col) =
                make_float2(tf32r(p00), tf32r(p01));
            *(float2*)(fsm + OFF_P + (rowa + 8) * 68 + col) =
                make_float2(tf32r(p10), tf32r(p11));
        }
        __syncthreads();

        // ---- S partial sums ----
        {
            int row = tid & 63, qtr = tid >> 6;
            const float* pr = fsm + OFF_P + row * 68 + qtr * 16;
            float s = 0.f;
#pragma unroll
            for (int i = 0; i < 16; i++) s += pr[i];
            s_acc += s;
        }
        // ---- Z += p~ @ KV (1x tf32) ----
#pragma unroll
        for (int ks = 0; ks < 8; ks++) {
            uint32_t a[2][4];
#pragma unroll
            for (int mt = 0; mt < 2; mt++) {
                int r = (wmz * 32 + mt * 16 + gid) * 68 + ks * 8 + tig;
                a[mt][0] = __float_as_uint(fsm[OFF_P + r]);
                a[mt][1] = __float_as_uint(fsm[OFF_P + r + 8 * 68]);
                a[mt][2] = __float_as_uint(fsm[OFF_P + r + 4]);
                a[mt][3] = __float_as_uint(fsm[OFF_P + r + 8 * 68 + 4]);
            }
#pragma unroll
            for (int nt = 0; nt < 16; nt++) {
                int c = wnz * 128 + nt * 8 + gid;
                uint32_t b0 = __float_as_uint(fsm[OFF_KV + (ks * 8 + tig) * 520 + c]);
                uint32_t b1 = __float_as_uint(fsm[OFF_KV + (ks * 8 + tig + 4) * 520 + c]);
                mma_tf32(zacc[0][nt], a[0][0], a[0][1], a[0][2], a[0][3], b0, b1);
                mma_tf32(zacc[1][nt], a[1][0], a[1][1], a[1][2], a[1][3], b0, b1);
            }
        }
    }

    // ---- Z regs -> smem (reuse KV area) ----
    __syncthreads();
#pragma unroll
    for (int mt = 0; mt < 2; mt++) {
        int row = wmz * 32 + mt * 16 + gid;
#pragma unroll
        for (int nt = 0; nt < 16; nt++) {
            int c = wnz * 128 + nt * 8 + tig * 2;
            *(float2*)(fsm + OFF_KV + row * 520 + c) =
                make_float2(zacc[mt][nt][0], zacc[mt][nt][1]);
            *(float2*)(fsm + OFF_KV + (row + 8) * 520 + c) =
                make_float2(zacc[mt][nt][2], zacc[mt][nt][3]);
        }
    }
    fsm[OFF_S + tid] = s_acc;
    __syncthreads();
    if (tid < 64) {
        float s = fsm[OFF_S + tid] + fsm[OFF_S + 64 + tid] +
                  fsm[OFF_S + 128 + tid] + fsm[OFF_S + 192 + tid];
        fsm[OFF_S + tid] = 1.f / s;
    }
    __syncthreads();

    // ---- octonion epilogue: y[t, h*64 + m*8 + k] ----
#pragma unroll
    for (int u2 = 0; u2 < 2; u2++) {
        int u = tid * 2 + u2;
        int row = u >> 3, m = u & 7;
        float invS = fsm[OFF_S + row];
        const float* q = qn + ((long)h * T_SEQ + r0 + row) * HD + m * 8;
        const float* z = fsm + OFF_KV + row * 520 + m * 64;

        float q8[8];
        float4 qa = *(const float4*)q, qb = *(const float4*)(q + 4);
        q8[0]=qa.x; q8[1]=qa.y; q8[2]=qa.z; q8[3]=qa.w;
        q8[4]=qb.x; q8[5]=qb.y; q8[6]=qb.z; q8[7]=qb.w;
        float acc[8] = {0,0,0,0,0,0,0,0};
#pragma unroll
        for (int p = 0; p < 8; p++) {
            float e[8] = {0,0,0,0,0,0,0,0};
            e[p] = 1.f;
            float uo[8], z8[8], w[8];
            omul8(q8, e, uo);       // folds to signed permutation
            float4 z0 = *(const float4*)(z + p * 8);
            float4 z1 = *(const float4*)(z + p * 8 + 4);
            z8[0]=z0.x; z8[1]=z0.y; z8[2]=z0.z; z8[3]=z0.w;
            z8[4]=z1.x; z8[5]=z1.y; z8[6]=z1.z; z8[7]=z1.w;
            omul8(uo, z8, w);
#pragma unroll
            for (int k = 0; k < 8; k++) acc[k] += w[k];
        }
        float* yo = y + (long)(r0 + row) * CEMB + h * HD + m * 8;
        *(float4*)yo = make_float4(acc[0]*invS, acc[1]*invS, acc[2]*invS, acc[3]*invS);
        *(float4*)(yo + 4) = make_float4(acc[4]*invS, acc[5]*invS, acc[6]*invS, acc[7]*invS);
    }
}

// ---------------- launch -----------------------------------------------------
extern "C" void kernel_launch(void* const* d_in, const int* in_sizes, int n_in,
                              void* d_out, int out_size)
{
    const float* x    = (const float*)d_in[0];
    const float* cosp = (const float*)d_in[1];
    const float* sinp = (const float*)d_in[2];
    const float* Wq   = (const float*)d_in[3];
    const float* Wk   = (const float*)d_in[4];
    const float* Wv   = (const float*)d_in[5];
    const float* Wo   = (const float*)d_in[6];
    float* out = (float*)d_out;

    float *qraw, *kraw, *vraw, *qn, *kn, *kv, *y;
    cudaGetSymbolAddress((void**)&qraw, g_qraw);
    cudaGetSymbolAddress((void**)&kraw, g_kraw);
    cudaGetSymbolAddress((void**)&vraw, g_vraw);
    cudaGetSymbolAddress((void**)&qn,   g_qn);
    cudaGetSymbolAddress((void**)&kn,   g_kn);
    cudaGetSymbolAddress((void**)&kv,   g_kv);
    cudaGetSymbolAddress((void**)&y,    g_y);

    const int smem_bf16 = 2 * 4 * BTILE_U * 4;   // 49152 B
    cudaFuncSetAttribute(qkv_gemm, cudaFuncAttributeMaxDynamicSharedMemorySize, smem_bf16);
    cudaFuncSetAttribute(wo_gemm,  cudaFuncAttributeMaxDynamicSharedMemorySize, smem_bf16);
    cudaFuncSetAttribute(fused_attn, cudaFuncAttributeMaxDynamicSharedMemorySize, FA_SMEM);

    // 1) merged QKV projections (3xBF16 split, NT)
    qkv_gemm<<<dim3(CEMB / 128, T_SEQ / 128, 3), 256, smem_bf16>>>(
        x, Wq, Wk, Wv, qraw, kraw, vraw);

    // 2) rotary + rms + octet-norm + tf32 KV outer products
    prep_kernel<<<dim3(NH, T_SEQ), 64>>>(qraw, kraw, vraw, cosp, sinp, qn, kn, kv);

    // 3) fused scores+softmax+Z+octonion-epilogue -> y
    fused_attn<<<dim3(T_SEQ / 64, NH), 256, FA_SMEM>>>(qn, kn, kv, y);

    // 4) out = y @ Wo^T (3xBF16 split)
    wo_gemm<<<dim3(CEMB / 128, T_SEQ / 128), 256, smem_bf16>>>(y, Wo, out);
}

// round 6
// speedup vs baseline: 1.1699x; 1.1699x over previous
#include <cuda_runtime.h>
#include <cstdint>
#include <math.h>

#define T_SEQ 2048
#define NH 16
#define HD 64
#define CEMB 1024
#define KVW 512

// ---------------- scratch (device globals) ----------------------------------
static __device__ float g_qraw[T_SEQ * CEMB];
static __device__ float g_kraw[T_SEQ * CEMB];
static __device__ float g_vraw[T_SEQ * CEMB];
static __device__ float g_qn[NH * T_SEQ * HD];
static __device__ float g_kv[NH * T_SEQ * KVW];         // [h][t][n], tf32-rounded
static __device__ uint32_t g_qbh[NH * T_SEQ * 32];      // q bf16-hi packed
static __device__ uint32_t g_qbl[NH * T_SEQ * 32];      // q bf16-lo packed
static __device__ uint32_t g_kbh[NH * T_SEQ * 32];
static __device__ uint32_t g_kbl[NH * T_SEQ * 32];
static __device__ float g_y[T_SEQ * CEMB];

// ---------------- helpers ----------------------------------------------------
static __device__ __forceinline__ uint32_t smem_u32(const void* p) {
    uint32_t a;
    asm("{ .reg .u64 t; cvta.to.shared.u64 t, %1; cvt.u32.u64 %0, t; }" : "=r"(a) : "l"(p));
    return a;
}
static __device__ __forceinline__ float tf32r(float x) {
    float y; asm("cvt.rna.tf32.f32 %0, %1;" : "=f"(y) : "f"(x)); return y;
}
static __device__ __forceinline__ void mma_tf32(
    float* acc, uint32_t a0, uint32_t a1, uint32_t a2, uint32_t a3,
    uint32_t b0, uint32_t b1)
{
    asm volatile(
        "mma.sync.aligned.m16n8k8.row.col.f32.tf32.tf32.f32 "
        "{%0,%1,%2,%3},{%4,%5,%6,%7},{%8,%9},{%0,%1,%2,%3};"
        : "+f"(acc[0]), "+f"(acc[1]), "+f"(acc[2]), "+f"(acc[3])
        : "r"(a0), "r"(a1), "r"(a2), "r"(a3), "r"(b0), "r"(b1));
}
static __device__ __forceinline__ void mma_bf16(
    float* acc, uint32_t a0, uint32_t a1, uint32_t a2, uint32_t a3,
    uint32_t b0, uint32_t b1)
{
    asm volatile(
        "mma.sync.aligned.m16n8k16.row.col.f32.bf16.bf16.f32 "
        "{%0,%1,%2,%3},{%4,%5,%6,%7},{%8,%9},{%0,%1,%2,%3};"
        : "+f"(acc[0]), "+f"(acc[1]), "+f"(acc[2]), "+f"(acc[3])
        : "r"(a0), "r"(a1), "r"(a2), "r"(a3), "r"(b0), "r"(b1));
}
static __device__ __forceinline__ uint2 pack_split(float f0, float f1) {
    uint32_t h;
    asm("cvt.rn.bf16x2.f32 %0, %1, %2;" : "=r"(h) : "f"(f1), "f"(f0));
    float h0 = __uint_as_float(h << 16);
    float h1 = __uint_as_float(h & 0xffff0000u);
    uint32_t l;
    float r0 = f0 - h0, r1 = f1 - h1;
    asm("cvt.rn.bf16x2.f32 %0, %1, %2;" : "=r"(l) : "f"(r1), "f"(r0));
    return make_uint2(h, l);
}
#define CP16(dst_u32, src_ptr) \
    asm volatile("cp.async.cg.shared.global [%0], [%1], 16;" \
                 :: "r"(dst_u32), "l"(src_ptr) : "memory")
#define CP_COMMIT() asm volatile("cp.async.commit_group;" ::: "memory")

// ================= bf16 3x-split GEMM body (NT) — unchanged (passing) ========
#define BSTR 12
#define BTILE_U (128 * BSTR)

static __device__ __forceinline__ void bf16_nt_body(
    const float* __restrict__ A, const float* __restrict__ B, float* __restrict__ C,
    int K, int lda, int ldb, int ldc, int m0, int n0)
{
    extern __shared__ uint32_t smu[];
    const int STAGE = 4 * BTILE_U;
    int nch = K >> 4;

    int tid = threadIdx.x;
    int lane = tid & 31, wid = tid >> 5;
    int gid = lane >> 2, tig = lane & 3;
    int warp_m = wid & 3, warp_n = wid >> 2;
    int arow = tid >> 1, akc = (tid & 1) * 8;

    float acc[2][8][4];
#pragma unroll
    for (int i = 0; i < 2; i++)
#pragma unroll
        for (int j = 0; j < 8; j++)
#pragma unroll
            for (int q = 0; q < 4; q++) acc[i][j][q] = 0.f;

    float4 ra0, ra1, rb0, rb1;
    auto LOADG = [&](int k0) {
        const float* ap = A + (long)(m0 + arow) * lda + k0 + akc;
        ra0 = *(const float4*)ap;
        ra1 = *(const float4*)(ap + 4);
        const float* bp = B + (long)(n0 + arow) * ldb + k0 + akc;
        rb0 = *(const float4*)bp;
        rb1 = *(const float4*)(bp + 4);
    };
    auto STORES = [&](int sb) {
        int ao = arow * BSTR + (akc >> 1);
        uint2 p0 = pack_split(ra0.x, ra0.y), p1 = pack_split(ra0.z, ra0.w);
        uint2 p2 = pack_split(ra1.x, ra1.y), p3 = pack_split(ra1.z, ra1.w);
        *(uint4*)(smu + sb + ao)               = make_uint4(p0.x, p1.x, p2.x, p3.x);
        *(uint4*)(smu + sb + 2 * BTILE_U + ao) = make_uint4(p0.y, p1.y, p2.y, p3.y);
        uint2 q0 = pack_split(rb0.x, rb0.y), q1 = pack_split(rb0.z, rb0.w);
        uint2 q2 = pack_split(rb1.x, rb1.y), q3 = pack_split(rb1.z, rb1.w);
        *(uint4*)(smu + sb + BTILE_U + ao)     = make_uint4(q0.x, q1.x, q2.x, q3.x);
        *(uint4*)(smu + sb + 3 * BTILE_U + ao) = make_uint4(q0.y, q1.y, q2.y, q3.y);
    };

    LOADG(0);
    STORES(0);
    __syncthreads();

    for (int ch = 0; ch < nch; ch++) {
        if (ch + 1 < nch) LOADG((ch + 1) << 4);
        int sb = (ch & 1) * STAGE;
#pragma unroll
        for (int p = 0; p < 3; p++) {
            const uint32_t* Abase = smu + sb + (p == 2 ? 2 * BTILE_U : 0);
            const uint32_t* Bbase = smu + sb + BTILE_U + (p == 1 ? 2 * BTILE_U : 0);
            uint32_t af[2][4];
#pragma unroll
            for (int mt = 0; mt < 2; mt++) {
                int r = (warp_m * 32 + mt * 16 + gid) * BSTR + tig;
                af[mt][0] = Abase[r];
                af[mt][1] = Abase[r + 8 * BSTR];
                af[mt][2] = Abase[r + 4];
                af[mt][3] = Abase[r + 8 * BSTR + 4];
            }
            uint32_t bfr[8][2];
#pragma unroll
            for (int nt = 0; nt < 8; nt++) {
                int c = (warp_n * 64 + nt * 8 + gid) * BSTR + tig;
                bfr[nt][0] = Bbase[c];
                bfr[nt][1] = Bbase[c + 4];
            }
#pragma unroll
            for (int mt = 0; mt < 2; mt++)
#pragma unroll
                for (int nt = 0; nt < 8; nt++)
                    mma_bf16(acc[mt][nt], af[mt][0], af[mt][1], af[mt][2],
                             af[mt][3], bfr[nt][0], bfr[nt][1]);
        }
        if (ch + 1 < nch) {
            __syncthreads();
            STORES(((ch + 1) & 1) * STAGE);
            __syncthreads();
        }
    }

#pragma unroll
    for (int mt = 0; mt < 2; mt++) {
        int r0 = m0 + warp_m * 32 + mt * 16 + gid;
#pragma unroll
        for (int nt = 0; nt < 8; nt++) {
            int c = n0 + warp_n * 64 + nt * 8 + tig * 2;
            *(float2*)(C + (long)r0 * ldc + c) =
                make_float2(acc[mt][nt][0], acc[mt][nt][1]);
            *(float2*)(C + (long)(r0 + 8) * ldc + c) =
                make_float2(acc[mt][nt][2], acc[mt][nt][3]);
        }
    }
}

__global__ void __launch_bounds__(256, 2) qkv_gemm(
    const float* __restrict__ x,
    const float* __restrict__ Wq, const float* __restrict__ Wk,
    const float* __restrict__ Wv,
    float* q, float* k, float* v)
{
    const float* B = blockIdx.z == 0 ? Wq : blockIdx.z == 1 ? Wk : Wv;
    float* C = blockIdx.z == 0 ? q : blockIdx.z == 1 ? k : v;
    bf16_nt_body(x, B, C, CEMB, CEMB, CEMB, CEMB,
                 blockIdx.y * 128, blockIdx.x * 128);
}

__global__ void __launch_bounds__(256, 2) wo_gemm(
    const float* __restrict__ y, const float* __restrict__ Wo, float* out)
{
    bf16_nt_body(y, Wo, out, CEMB, CEMB, CEMB, CEMB,
                 blockIdx.y * 128, blockIdx.x * 128);
}

// ---------------- prep: rotary + RMS + octet norm + KV + bf16 packing -------
__global__ __launch_bounds__(64) void prep_kernel(
    const float* __restrict__ qraw, const float* __restrict__ kraw,
    const float* __restrict__ vraw,
    const float* __restrict__ cosp, const float* __restrict__ sinp,
    float* __restrict__ qn, float* __restrict__ kv,
    uint32_t* __restrict__ qbh, uint32_t* __restrict__ qbl,
    uint32_t* __restrict__ kbh, uint32_t* __restrict__ kbl)
{
    int h = blockIdx.x, t = blockIdx.y, d = threadIdx.x;
    __shared__ float r1[64], r2[64], skc[64], sv[64], sq[64], sk[64];

    long base = (long)t * CEMB + h * HD;
    int j = d & 31;
    float c = cosp[t * 32 + j], s = sinp[t * 32 + j];

    float x1q = qraw[base + j], x2q = qraw[base + j + 32];
    float qv = (d < 32) ? (x1q * c + x2q * s) : (x2q * c - x1q * s);
    float x1k = kraw[base + j], x2k = kraw[base + j + 32];
    float kvv = (d < 32) ? (x1k * c + x2k * s) : (x2k * c - x1k * s);

    r1[d] = qv * qv;
    r2[d] = kvv * kvv;
    __syncthreads();
#pragma unroll
    for (int off = 32; off > 0; off >>= 1) {
        if (d < off) { r1[d] += r1[d + off]; r2[d] += r2[d + off]; }
        __syncthreads();
    }
    float rq = rsqrtf(r1[0] * (1.f / 64.f) + 1e-6f);
    float rk = rsqrtf(r2[0] * (1.f / 64.f) + 1e-6f);
    float qno = qv * rq, kno = kvv * rk;

    long nbase = ((long)h * T_SEQ + t) * HD + d;
    qn[nbase] = qno;
    sq[d] = qno;
    sk[d] = kno;

    float o = kno * kno;
    o += __shfl_xor_sync(0xffffffffu, o, 1);
    o += __shfl_xor_sync(0xffffffffu, o, 2);
    o += __shfl_xor_sync(0xffffffffu, o, 4);
    float ko = kno / fmaxf(sqrtf(o), 1e-12f);
    skc[d] = ((d & 7) == 0) ? ko : -ko;
    sv[d] = vraw[base + d];
    __syncthreads();

    float kc = skc[d];
    int mb = d & ~7;
    float* row = kv + ((long)h * T_SEQ + t) * KVW + d * 8;
    float4 a = make_float4(tf32r(kc * sv[mb + 0]), tf32r(kc * sv[mb + 1]),
                           tf32r(kc * sv[mb + 2]), tf32r(kc * sv[mb + 3]));
    float4 b = make_float4(tf32r(kc * sv[mb + 4]), tf32r(kc * sv[mb + 5]),
                           tf32r(kc * sv[mb + 6]), tf32r(kc * sv[mb + 7]));
    *(float4*)row = a;
    *(float4*)(row + 4) = b;

    // bf16 hi/lo packing (32 words per row)
    long pbase = ((long)h * T_SEQ + t) * 32;
    if (d < 32) {
        uint2 p = pack_split(sq[2 * d], sq[2 * d + 1]);
        qbh[pbase + d] = p.x;
        qbl[pbase + d] = p.y;
    } else {
        int d2 = d - 32;
        uint2 p = pack_split(sk[2 * d2], sk[2 * d2 + 1]);
        kbh[pbase + d2] = p.x;
        kbl[pbase + d2] = p.y;
    }
}

// ---------------- octonion math ----------------------------------------------
__device__ __forceinline__ void qmul4(const float* q1, const float* q2, float* r)
{
    r[0] = q1[0]*q2[0] - q1[1]*q2[1] - q1[2]*q2[2] - q1[3]*q2[3];
    r[1] = q1[0]*q2[1] + q1[1]*q2[0] + q1[2]*q2[3] - q1[3]*q2[2];
    r[2] = q1[0]*q2[2] - q1[1]*q2[3] + q1[2]*q2[0] + q1[3]*q2[1];
    r[3] = q1[0]*q2[3] + q1[1]*q2[2] - q1[2]*q2[1] + q1[3]*q2[0];
}
__device__ __forceinline__ void omul8(const float* o1, const float* o2, float* r)
{
    const float* a = o1; const float* b = o1 + 4;
    const float* c = o2; const float* d = o2 + 4;
    float dc[4] = { d[0], -d[1], -d[2], -d[3] };
    float cc[4] = { c[0], -c[1], -c[2], -c[3] };
    float t1[4], t2[4];
    qmul4(a, c, t1); qmul4(dc, b, t2);
    r[0] = t1[0] - t2[0]; r[1] = t1[1] - t2[1];
    r[2] = t1[2] - t2[2]; r[3] = t1[3] - t2[3];
    qmul4(d, a, t1); qmul4(b, cc, t2);
    r[4] = t1[0] + t2[0]; r[5] = t1[1] + t2[1];
    r[6] = t1[2] + t2[2]; r[7] = t1[3] + t2[3];
}

// ================= fused attention (512 threads, cp.async pipelined) =========
// CTA = (head, 64 q rows). 32-key tiles, double-buffered KV + bf16 k tiles.
#define TK 32
// word offsets in dynamic smem
#define OFF_KV 0
#define KV_STG 16640           // 32 * 520
#define OFF_P  33280           // 64 * 36
#define OFF_QH 35584           // 64 * 36
#define OFF_QL 37888
#define OFF_KH 40192           // 2 stages * 32*36
#define KH_STG 1152
#define OFF_KL 42496
#define OFF_S  44800           // 512
#define FA_SMEM ((OFF_S + 512) * 4)

__global__ void __launch_bounds__(512, 1) fused_attn(
    const float* __restrict__ qn,
    const uint32_t* __restrict__ qbh, const uint32_t* __restrict__ qbl,
    const uint32_t* __restrict__ kbh, const uint32_t* __restrict__ kbl,
    const float* __restrict__ kv, float* __restrict__ y)
{
    extern __shared__ __align__(16) float fsm[];
    uint32_t* usm = (uint32_t*)fsm;
    uint32_t sbase = smem_u32(fsm);

    int qt = 31 - blockIdx.x;           // biggest tiles first
    int h = blockIdx.y;
    int r0 = qt * 64;
    int njt = 2 * qt + 2;

    int tid = threadIdx.x, lane = tid & 31, wid = tid >> 5;
    int gid = lane >> 2, tig = lane & 3;
    int wms = wid & 3, wns = wid >> 2;  // scores: rows wms*16, cols wns*8
    int wmz = wid & 1, wnz = wid >> 1;  // Z: rows wmz*32, cols wnz*64

    const float*    kvh = kv  + (long)h * T_SEQ * KVW;
    const uint32_t* khh = kbh + (long)h * T_SEQ * 32;
    const uint32_t* khl = kbl + (long)h * T_SEQ * 32;

    // --- async tile loader: KV rows 32x512 f32 + k bf16 hi/lo 32x32 u32 ---
    int kv_row = tid >> 4, kv_c0 = (tid & 15) * 32;
    int kar = tid >> 8, krr = (tid >> 3) & 31, kcc = (tid & 7) * 4;
    const uint32_t* ksrcb = (kar ? khl : khh);
    uint32_t kdst_base = sbase + ((kar ? OFF_KL : OFF_KH) + krr * 36 + kcc) * 4;

    auto issue_tile = [&](int jt, int s) {
        const float* src = kvh + (long)(jt * TK + kv_row) * KVW + kv_c0;
        uint32_t dst = sbase + (OFF_KV + s * KV_STG + kv_row * 520 + kv_c0) * 4;
#pragma unroll
        for (int i = 0; i < 8; i++) CP16(dst + i * 16, src + i * 4);
        CP16(kdst_base + s * KH_STG * 4, ksrcb + (long)(jt * TK + krr) * 32 + kcc);
    };

    // --- prologue: Q tiles + tile 0 ---
    {
        const uint32_t* qhh = qbh + ((long)h * T_SEQ + r0) * 32;
        const uint32_t* qhl = qbl + ((long)h * T_SEQ + r0) * 32;
#pragma unroll
        for (int i = 0; i < 2; i++) {
            int idx = tid + i * 512;
            int arr = idx >> 9, rr = (idx >> 3) & 63, cc = (idx & 7) * 4;
            const uint32_t* src = (arr ? qhl : qhh) + (long)rr * 32 + cc;
            uint32_t dst = sbase + ((arr ? OFF_QL : OFF_QH) + rr * 36 + cc) * 4;
            CP16(dst, src);
        }
        issue_tile(0, 0);
        CP_COMMIT();
    }

    float zacc[2][8][4];
#pragma unroll
    for (int i = 0; i < 2; i++)
#pragma unroll
        for (int j = 0; j < 8; j++)
#pragma unroll
            for (int q = 0; q < 4; q++) zacc[i][j][q] = 0.f;
    float s_acc = 0.f;

    for (int jt = 0; jt < njt; jt++) {
        int s = jt & 1;
        if (jt + 1 < njt) {
            issue_tile(jt + 1, s ^ 1);
            CP_COMMIT();
            asm volatile("cp.async.wait_group 1;" ::: "memory");
        } else {
            asm volatile("cp.async.wait_group 0;" ::: "memory");
        }
        __syncthreads();

        // ---- scores (3x bf16 split): warp tile 16 rows x 8 cols ----
        float sacc[4] = {0.f, 0.f, 0.f, 0.f};
        {
            int ra_base = (wms * 16 + gid) * 36 + tig;
            int rb_base = (wns * 8 + gid) * 36 + tig;
#pragma unroll
            for (int ks = 0; ks < 4; ks++) {
#pragma unroll
                for (int p = 0; p < 3; p++) {
                    const uint32_t* Ab = usm + (p == 2 ? OFF_QL : OFF_QH);
                    const uint32_t* Bb = usm + (p == 1 ? OFF_KL : OFF_KH) + s * KH_STG;
                    int ra = ra_base + ks * 8;
                    int rb = rb_base + ks * 8;
                    mma_bf16(sacc, Ab[ra], Ab[ra + 8 * 36], Ab[ra + 4],
                             Ab[ra + 8 * 36 + 4], Bb[rb], Bb[rb + 4]);
                }
            }
        }
        // ---- exp + causal mask + store p~ (tf32) ----
        {
            int rowa = wms * 16 + gid;
            int col = wns * 8 + tig * 2;
            int j0 = jt * TK;
            float p00 = __expf(sacc[0] * 0.125f);
            float p01 = __expf(sacc[1] * 0.125f);
            float p10 = __expf(sacc[2] * 0.125f);
            float p11 = __expf(sacc[3] * 0.125f);
            if (jt >= njt - 2) {
                if (j0 + col     > r0 + rowa)     p00 = 0.f;
                if (j0 + col + 1 > r0 + rowa)     p01 = 0.f;
                if (j0 + col     > r0 + rowa + 8) p10 = 0.f;
                if (j0 + col + 1 > r0 + rowa + 8) p11 = 0.f;
            }
            *(float2*)(fsm + OFF_P + rowa * 36 + col) =
                make_float2(tf32r(p00), tf32r(p01));
            *(float2*)(fsm + OFF_P + (rowa + 8) * 36 + col) =
                make_float2(tf32r(p10), tf32r(p11));
        }
        __syncthreads();

        // ---- S partial sums (8 threads per row x 4 cols) ----
        {
            int row = tid & 63, part = tid >> 6;
            const float* pr = fsm + OFF_P + row * 36 + part * 4;
            s_acc += pr[0] + pr[1] + pr[2] + pr[3];
        }
        // ---- Z += p~ @ KV (1x tf32): warp tile 32 rows x 64 cols ----
        {
            const float* KVs = fsm + OFF_KV + s * KV_STG;
#pragma unroll
            for (int ks = 0; ks < 4; ks++) {
                uint32_t a[2][4];
#pragma unroll
                for (int mt = 0; mt < 2; mt++) {
                    int r = (wmz * 32 + mt * 16 + gid) * 36 + ks * 8 + tig;
                    a[mt][0] = __float_as_uint(fsm[OFF_P + r]);
                    a[mt][1] = __float_as_uint(fsm[OFF_P + r + 8 * 36]);
                    a[mt][2] = __float_as_uint(fsm[OFF_P + r + 4]);
                    a[mt][3] = __float_as_uint(fsm[OFF_P + r + 8 * 36 + 4]);
                }
#pragma unroll
                for (int nt = 0; nt < 8; nt++) {
                    int c = wnz * 64 + nt * 8 + gid;
                    uint32_t b0 = __float_as_uint(KVs[(ks * 8 + tig) * 520 + c]);
                    uint32_t b1 = __float_as_uint(KVs[(ks * 8 + tig + 4) * 520 + c]);
                    mma_tf32(zacc[0][nt], a[0][0], a[0][1], a[0][2], a[0][3], b0, b1);
                    mma_tf32(zacc[1][nt], a[1][0], a[1][1], a[1][2], a[1][3], b0, b1);
                }
            }
        }
        __syncthreads();
    }

    // ---- Z regs -> smem (reuse both KV stages: 64 x 520) ----
#pragma unroll
    for (int mt = 0; mt < 2; mt++) {
        int row = wmz * 32 + mt * 16 + gid;
#pragma unroll
        for (int nt = 0; nt < 8; nt++) {
            int c = wnz * 64 + nt * 8 + tig * 2;
            *(float2*)(fsm + OFF_KV + row * 520 + c) =
                make_float2(zacc[mt][nt][0], zacc[mt][nt][1]);
            *(float2*)(fsm + OFF_KV + (row + 8) * 520 + c) =
                make_float2(zacc[mt][nt][2], zacc[mt][nt][3]);
        }
    }
    {
        int row = tid & 63, part = tid >> 6;
        fsm[OFF_S + part * 64 + row] = s_acc;
    }
    __syncthreads();
    if (tid < 64) {
        float sum = 0.f;
#pragma unroll
        for (int p = 0; p < 8; p++) sum += fsm[OFF_S + p * 64 + tid];
        fsm[OFF_S + tid] = 1.f / sum;
    }
    __syncthreads();

    // ---- octonion epilogue: one (row, m) unit per thread ----
    {
        int row = tid >> 3, m = tid & 7;
        float invS = fsm[OFF_S + row];
        const float* q = qn + ((long)h * T_SEQ + r0 + row) * HD + m * 8;
        const float* z = fsm + OFF_KV + row * 520 + m * 64;

        float q8[8];
        float4 qa = *(const float4*)q, qb = *(const float4*)(q + 4);
        q8[0]=qa.x; q8[1]=qa.y; q8[2]=qa.z; q8[3]=qa.w;
        q8[4]=qb.x; q8[5]=qb.y; q8[6]=qb.z; q8[7]=qb.w;
        float acc[8] = {0,0,0,0,0,0,0,0};
#pragma unroll
        for (int p = 0; p < 8; p++) {
            float e[8] = {0,0,0,0,0,0,0,0};
            e[p] = 1.f;
            float uo[8], z8[8], w[8];
            omul8(q8, e, uo);   // folds to signed permutation
            float4 z0 = *(const float4*)(z + p * 8);
            float4 z1 = *(const float4*)(z + p * 8 + 4);
            z8[0]=z0.x; z8[1]=z0.y; z8[2]=z0.z; z8[3]=z0.w;
            z8[4]=z1.x; z8[5]=z1.y; z8[6]=z1.z; z8[7]=z1.w;
            omul8(uo, z8, w);
#pragma unroll
            for (int k = 0; k < 8; k++) acc[k] += w[k];
        }
        float* yo = y + (long)(r0 + row) * CEMB + h * HD + m * 8;
        *(float4*)yo = make_float4(acc[0]*invS, acc[1]*invS, acc[2]*invS, acc[3]*invS);
        *(float4*)(yo + 4) = make_float4(acc[4]*invS, acc[5]*invS, acc[6]*invS, acc[7]*invS);
    }
}

// ---------------- launch -----------------------------------------------------
extern "C" void kernel_launch(void* const* d_in, const int* in_sizes, int n_in,
                              void* d_out, int out_size)
{
    const float* x    = (const float*)d_in[0];
    const float* cosp = (const float*)d_in[1];
    const float* sinp = (const float*)d_in[2];
    const float* Wq   = (const float*)d_in[3];
    const float* Wk   = (const float*)d_in[4];
    const float* Wv   = (const float*)d_in[5];
    const float* Wo   = (const float*)d_in[6];
    float* out = (float*)d_out;

    float *qraw, *kraw, *vraw, *qn, *kv, *y;
    uint32_t *qbh, *qbl, *kbh, *kbl;
    cudaGetSymbolAddress((void**)&qraw, g_qraw);
    cudaGetSymbolAddress((void**)&kraw, g_kraw);
    cudaGetSymbolAddress((void**)&vraw, g_vraw);
    cudaGetSymbolAddress((void**)&qn,   g_qn);
    cudaGetSymbolAddress((void**)&kv,   g_kv);
    cudaGetSymbolAddress((void**)&qbh,  g_qbh);
    cudaGetSymbolAddress((void**)&qbl,  g_qbl);
    cudaGetSymbolAddress((void**)&kbh,  g_kbh);
    cudaGetSymbolAddress((void**)&kbl,  g_kbl);
    cudaGetSymbolAddress((void**)&y,    g_y);

    const int smem_bf16 = 2 * 4 * BTILE_U * 4;   // 49152 B
    cudaFuncSetAttribute(qkv_gemm, cudaFuncAttributeMaxDynamicSharedMemorySize, smem_bf16);
    cudaFuncSetAttribute(wo_gemm,  cudaFuncAttributeMaxDynamicSharedMemorySize, smem_bf16);
    cudaFuncSetAttribute(fused_attn, cudaFuncAttributeMaxDynamicSharedMemorySize, FA_SMEM);

    // 1) merged QKV projections (3xBF16 split, NT)
    qkv_gemm<<<dim3(CEMB / 128, T_SEQ / 128, 3), 256, smem_bf16>>>(
        x, Wq, Wk, Wv, qraw, kraw, vraw);

    // 2) rotary + rms + octet-norm + tf32 KV + bf16 packing
    prep_kernel<<<dim3(NH, T_SEQ), 64>>>(qraw, kraw, vraw, cosp, sinp,
                                         qn, kv, qbh, qbl, kbh, kbl);

    // 3) fused scores+softmax+Z+octonion-epilogue -> y
    fused_attn<<<dim3(32, NH), 512, FA_SMEM>>>(qn, qbh, qbl, kbh, kbl, kv, y);

    // 4) out = y @ Wo^T (3xBF16 split)
    wo_gemm<<<dim3(CEMB / 128, T_SEQ / 128), 256, smem_bf16>>>(y, Wo, out);
}

// round 7
// speedup vs baseline: 1.5595x; 1.3331x over previous
#include <cuda_runtime.h>
#include <cstdint>
#include <math.h>

#define T_SEQ 2048
#define NH 16
#define HD 64
#define CEMB 1024
#define KVW 512

// ---------------- scratch (device globals) ----------------------------------
static __device__ float g_qraw[T_SEQ * CEMB];
static __device__ float g_kraw[T_SEQ * CEMB];
static __device__ float g_vraw[T_SEQ * CEMB];
static __device__ float g_qn[NH * T_SEQ * HD];
static __device__ float g_kvp[NH * T_SEQ * KVW];        // paired layout [h][g][c][w']
static __device__ uint32_t g_qbh[NH * T_SEQ * 32];      // q bf16-hi packed (permuted words)
static __device__ uint32_t g_qbl[NH * T_SEQ * 32];
static __device__ uint32_t g_kbh[NH * T_SEQ * 32];
static __device__ uint32_t g_kbl[NH * T_SEQ * 32];
static __device__ float g_y[T_SEQ * CEMB];

// ---------------- helpers ----------------------------------------------------
static __device__ __forceinline__ uint32_t smem_u32(const void* p) {
    uint32_t a;
    asm("{ .reg .u64 t; cvta.to.shared.u64 t, %1; cvt.u32.u64 %0, t; }" : "=r"(a) : "l"(p));
    return a;
}
static __device__ __forceinline__ float tf32r(float x) {
    float y; asm("cvt.rna.tf32.f32 %0, %1;" : "=f"(y) : "f"(x)); return y;
}
static __device__ __forceinline__ void mma_tf32(
    float* acc, uint32_t a0, uint32_t a1, uint32_t a2, uint32_t a3,
    uint32_t b0, uint32_t b1)
{
    asm volatile(
        "mma.sync.aligned.m16n8k8.row.col.f32.tf32.tf32.f32 "
        "{%0,%1,%2,%3},{%4,%5,%6,%7},{%8,%9},{%0,%1,%2,%3};"
        : "+f"(acc[0]), "+f"(acc[1]), "+f"(acc[2]), "+f"(acc[3])
        : "r"(a0), "r"(a1), "r"(a2), "r"(a3), "r"(b0), "r"(b1));
}
static __device__ __forceinline__ void mma_bf16(
    float* acc, uint32_t a0, uint32_t a1, uint32_t a2, uint32_t a3,
    uint32_t b0, uint32_t b1)
{
    asm volatile(
        "mma.sync.aligned.m16n8k16.row.col.f32.bf16.bf16.f32 "
        "{%0,%1,%2,%3},{%4,%5,%6,%7},{%8,%9},{%0,%1,%2,%3};"
        : "+f"(acc[0]), "+f"(acc[1]), "+f"(acc[2]), "+f"(acc[3])
        : "r"(a0), "r"(a1), "r"(a2), "r"(a3), "r"(b0), "r"(b1));
}
static __device__ __forceinline__ uint2 pack_split(float f0, float f1) {
    uint32_t h;
    asm("cvt.rn.bf16x2.f32 %0, %1, %2;" : "=r"(h) : "f"(f1), "f"(f0));
    float h0 = __uint_as_float(h << 16);
    float h1 = __uint_as_float(h & 0xffff0000u);
    uint32_t l;
    float r0 = f0 - h0, r1 = f1 - h1;
    asm("cvt.rn.bf16x2.f32 %0, %1, %2;" : "=r"(l) : "f"(r1), "f"(r0));
    return make_uint2(h, l);
}
#define CP16(dst_u32, src_ptr) \
    asm volatile("cp.async.cg.shared.global [%0], [%1], 16;" \
                 :: "r"(dst_u32), "l"(src_ptr) : "memory")
#define CP_COMMIT() asm volatile("cp.async.commit_group;" ::: "memory")

// pair-permutation within 8-element group: c -> (c&3)*2 + (c>>2)
static __device__ __forceinline__ int permw(int d) {
    return (d & ~7) + ((d & 3) * 2 + ((d & 7) >> 2));
}

// ================= bf16 3x-split GEMM body (NT) — unchanged (passing) ========
#define BSTR 12
#define BTILE_U (128 * BSTR)

static __device__ __forceinline__ void bf16_nt_body(
    const float* __restrict__ A, const float* __restrict__ B, float* __restrict__ C,
    int K, int lda, int ldb, int ldc, int m0, int n0)
{
    extern __shared__ uint32_t smu[];
    const int STAGE = 4 * BTILE_U;
    int nch = K >> 4;

    int tid = threadIdx.x;
    int lane = tid & 31, wid = tid >> 5;
    int gid = lane >> 2, tig = lane & 3;
    int warp_m = wid & 3, warp_n = wid >> 2;
    int arow = tid >> 1, akc = (tid & 1) * 8;

    float acc[2][8][4];
#pragma unroll
    for (int i = 0; i < 2; i++)
#pragma unroll
        for (int j = 0; j < 8; j++)
#pragma unroll
            for (int q = 0; q < 4; q++) acc[i][j][q] = 0.f;

    float4 ra0, ra1, rb0, rb1;
    auto LOADG = [&](int k0) {
        const float* ap = A + (long)(m0 + arow) * lda + k0 + akc;
        ra0 = *(const float4*)ap;
        ra1 = *(const float4*)(ap + 4);
        const float* bp = B + (long)(n0 + arow) * ldb + k0 + akc;
        rb0 = *(const float4*)bp;
        rb1 = *(const float4*)(bp + 4);
    };
    auto STORES = [&](int sb) {
        int ao = arow * BSTR + (akc >> 1);
        uint2 p0 = pack_split(ra0.x, ra0.y), p1 = pack_split(ra0.z, ra0.w);
        uint2 p2 = pack_split(ra1.x, ra1.y), p3 = pack_split(ra1.z, ra1.w);
        *(uint4*)(smu + sb + ao)               = make_uint4(p0.x, p1.x, p2.x, p3.x);
        *(uint4*)(smu + sb + 2 * BTILE_U + ao) = make_uint4(p0.y, p1.y, p2.y, p3.y);
        uint2 q0 = pack_split(rb0.x, rb0.y), q1 = pack_split(rb0.z, rb0.w);
        uint2 q2 = pack_split(rb1.x, rb1.y), q3 = pack_split(rb1.z, rb1.w);
        *(uint4*)(smu + sb + BTILE_U + ao)     = make_uint4(q0.x, q1.x, q2.x, q3.x);
        *(uint4*)(smu + sb + 3 * BTILE_U + ao) = make_uint4(q0.y, q1.y, q2.y, q3.y);
    };

    LOADG(0);
    STORES(0);
    __syncthreads();

    for (int ch = 0; ch < nch; ch++) {
        if (ch + 1 < nch) LOADG((ch + 1) << 4);
        int sb = (ch & 1) * STAGE;
#pragma unroll
        for (int p = 0; p < 3; p++) {
            const uint32_t* Abase = smu + sb + (p == 2 ? 2 * BTILE_U : 0);
            const uint32_t* Bbase = smu + sb + BTILE_U + (p == 1 ? 2 * BTILE_U : 0);
            uint32_t af[2][4];
#pragma unroll
            for (int mt = 0; mt < 2; mt++) {
                int r = (warp_m * 32 + mt * 16 + gid) * BSTR + tig;
                af[mt][0] = Abase[r];
                af[mt][1] = Abase[r + 8 * BSTR];
                af[mt][2] = Abase[r + 4];
                af[mt][3] = Abase[r + 8 * BSTR + 4];
            }
            uint32_t bfr[8][2];
#pragma unroll
            for (int nt = 0; nt < 8; nt++) {
                int c = (warp_n * 64 + nt * 8 + gid) * BSTR + tig;
                bfr[nt][0] = Bbase[c];
                bfr[nt][1] = Bbase[c + 4];
            }
#pragma unroll
            for (int mt = 0; mt < 2; mt++)
#pragma unroll
                for (int nt = 0; nt < 8; nt++)
                    mma_bf16(acc[mt][nt], af[mt][0], af[mt][1], af[mt][2],
                             af[mt][3], bfr[nt][0], bfr[nt][1]);
        }
        if (ch + 1 < nch) {
            __syncthreads();
            STORES(((ch + 1) & 1) * STAGE);
            __syncthreads();
        }
    }

#pragma unroll
    for (int mt = 0; mt < 2; mt++) {
        int r0 = m0 + warp_m * 32 + mt * 16 + gid;
#pragma unroll
        for (int nt = 0; nt < 8; nt++) {
            int c = n0 + warp_n * 64 + nt * 8 + tig * 2;
            *(float2*)(C + (long)r0 * ldc + c) =
                make_float2(acc[mt][nt][0], acc[mt][nt][1]);
            *(float2*)(C + (long)(r0 + 8) * ldc + c) =
                make_float2(acc[mt][nt][2], acc[mt][nt][3]);
        }
    }
}

__global__ void __launch_bounds__(256, 2) qkv_gemm(
    const float* __restrict__ x,
    const float* __restrict__ Wq, const float* __restrict__ Wk,
    const float* __restrict__ Wv,
    float* q, float* k, float* v)
{
    const float* B = blockIdx.z == 0 ? Wq : blockIdx.z == 1 ? Wk : Wv;
    float* C = blockIdx.z == 0 ? q : blockIdx.z == 1 ? k : v;
    bf16_nt_body(x, B, C, CEMB, CEMB, CEMB, CEMB,
                 blockIdx.y * 128, blockIdx.x * 128);
}

__global__ void __launch_bounds__(256, 2) wo_gemm(
    const float* __restrict__ y, const float* __restrict__ Wo, float* out)
{
    bf16_nt_body(y, Wo, out, CEMB, CEMB, CEMB, CEMB,
                 blockIdx.y * 128, blockIdx.x * 128);
}

// ---------------- prep: 8 keys per block; paired KV + permuted bf16 packing --
__global__ __launch_bounds__(512) void prep_kernel(
    const float* __restrict__ qraw, const float* __restrict__ kraw,
    const float* __restrict__ vraw,
    const float* __restrict__ cosp, const float* __restrict__ sinp,
    float* __restrict__ qn, float* __restrict__ kvp,
    uint32_t* __restrict__ qbh, uint32_t* __restrict__ qbl,
    uint32_t* __restrict__ kbh, uint32_t* __restrict__ kbl)
{
    int h = blockIdx.x, g = blockIdx.y;
    int tid = threadIdx.x;
    int w = tid >> 6, d = tid & 63;
    int t = g * 8 + w;

    __shared__ float r1[8][64], r2[8][64], skc[8][64], sv[8][64];
    __shared__ float sq[8][64], sk[8][64];
    __shared__ float kvstage[8][512];

    long base = (long)t * CEMB + h * HD;
    int j = d & 31;
    float c = cosp[t * 32 + j], s = sinp[t * 32 + j];

    float x1q = qraw[base + j], x2q = qraw[base + j + 32];
    float qv = (d < 32) ? (x1q * c + x2q * s) : (x2q * c - x1q * s);
    float x1k = kraw[base + j], x2k = kraw[base + j + 32];
    float kvv = (d < 32) ? (x1k * c + x2k * s) : (x2k * c - x1k * s);

    r1[w][d] = qv * qv;
    r2[w][d] = kvv * kvv;
    __syncthreads();
#pragma unroll
    for (int off = 32; off > 0; off >>= 1) {
        if (d < off) { r1[w][d] += r1[w][d + off]; r2[w][d] += r2[w][d + off]; }
        __syncthreads();
    }
    float rq = rsqrtf(r1[w][0] * (1.f / 64.f) + 1e-6f);
    float rk = rsqrtf(r2[w][0] * (1.f / 64.f) + 1e-6f);
    float qno = qv * rq, kno = kvv * rk;

    qn[((long)h * T_SEQ + t) * HD + d] = qno;
    sq[w][d] = qno;
    sk[w][d] = kno;

    float o = kno * kno;
    o += __shfl_xor_sync(0xffffffffu, o, 1);
    o += __shfl_xor_sync(0xffffffffu, o, 2);
    o += __shfl_xor_sync(0xffffffffu, o, 4);
    float ko = kno / fmaxf(sqrtf(o), 1e-12f);
    skc[w][d] = ((d & 7) == 0) ? ko : -ko;
    sv[w][d] = vraw[base + d];
    __syncthreads();

    // KV row (tf32-rounded) into stage
    {
        float kc = skc[w][d];
        int mb = d & ~7;
#pragma unroll
        for (int i = 0; i < 8; i++)
            kvstage[w][d * 8 + i] = tf32r(kc * sv[w][mb + i]);
    }

    // bf16 hi/lo packing with word permutation
    {
        long pbase = ((long)h * T_SEQ + t) * 32;
        if (d < 32) {
            uint2 p = pack_split(sq[w][2 * d], sq[w][2 * d + 1]);
            qbh[pbase + permw(d)] = p.x;
            qbl[pbase + permw(d)] = p.y;
        } else {
            int d2 = d - 32;
            uint2 p = pack_split(sk[w][2 * d2], sk[w][2 * d2 + 1]);
            kbh[pbase + permw(d2)] = p.x;
            kbl[pbase + permw(d2)] = p.y;
        }
    }
    __syncthreads();

    // paired coalesced write: kvp[((h*256+g)*512 + c)*8 + w'],
    // w' = (w&3)*2 + (w>>2)  <=>  w = (w'>>1) + (w'&1)*4
    float* outb = kvp + ((long)(h * 256 + g) * 512) * 8;
#pragma unroll
    for (int it = 0; it < 2; it++) {
        int idx = tid + it * 512;            // 0..1023 float4 units
        int cc = idx >> 1, half = idx & 1;
        float4 v;
        v.x = kvstage[((half * 4 + 0) >> 1) + ((half * 4 + 0) & 1) * 4][cc];
        v.y = kvstage[((half * 4 + 1) >> 1) + ((half * 4 + 1) & 1) * 4][cc];
        v.z = kvstage[((half * 4 + 2) >> 1) + ((half * 4 + 2) & 1) * 4][cc];
        v.w = kvstage[((half * 4 + 3) >> 1) + ((half * 4 + 3) & 1) * 4][cc];
        *(float4*)(outb + cc * 8 + half * 4) = v;
    }
}

// ---------------- octonion math ----------------------------------------------
__device__ __forceinline__ void qmul4(const float* q1, const float* q2, float* r)
{
    r[0] = q1[0]*q2[0] - q1[1]*q2[1] - q1[2]*q2[2] - q1[3]*q2[3];
    r[1] = q1[0]*q2[1] + q1[1]*q2[0] + q1[2]*q2[3] - q1[3]*q2[2];
    r[2] = q1[0]*q2[2] - q1[1]*q2[3] + q1[2]*q2[0] + q1[3]*q2[1];
    r[3] = q1[0]*q2[3] + q1[1]*q2[2] - q1[2]*q2[1] + q1[3]*q2[0];
}
__device__ __forceinline__ void omul8(const float* o1, const float* o2, float* r)
{
    const float* a = o1; const float* b = o1 + 4;
    const float* c = o2; const float* d = o2 + 4;
    float dc[4] = { d[0], -d[1], -d[2], -d[3] };
    float cc[4] = { c[0], -c[1], -c[2], -c[3] };
    float t1[4], t2[4];
    qmul4(a, c, t1); qmul4(dc, b, t2);
    r[0] = t1[0] - t2[0]; r[1] = t1[1] - t2[1];
    r[2] = t1[2] - t2[2]; r[3] = t1[3] - t2[3];
    qmul4(d, a, t1); qmul4(b, cc, t2);
    r[4] = t1[0] + t2[0]; r[5] = t1[1] + t2[1];
    r[6] = t1[2] + t2[2]; r[7] = t1[3] + t2[3];
}

// ================= fused attention (512 thr, LDS.64 fragment feeds) ==========
#define TK 32
// word offsets in dynamic smem
#define OFF_KV 0
#define KV_STG 16384            // 4ks * 512c * 8w'
#define OFF_P  32768            // 64 x 40
#define OFF_QH 35328            // 64 x 40
#define OFF_QL 37888
#define OFF_KH 40448            // 2 stages x 32x40
#define KH_STG 1280
#define OFF_KL 43008
#define OFF_S  45568            // 4 x 64
#define FA_SMEM ((OFF_S + 256) * 4)

__global__ void __launch_bounds__(512, 1) fused_attn(
    const float* __restrict__ qn,
    const uint32_t* __restrict__ qbh, const uint32_t* __restrict__ qbl,
    const uint32_t* __restrict__ kbh, const uint32_t* __restrict__ kbl,
    const float* __restrict__ kvp, float* __restrict__ y)
{
    extern __shared__ __align__(16) float fsm[];
    uint32_t* usm = (uint32_t*)fsm;
    uint32_t sbase = smem_u32(fsm);

    int qt = 31 - blockIdx.x;           // biggest tiles first
    int h = blockIdx.y;
    int r0 = qt * 64;
    int njt = 2 * qt + 2;

    int tid = threadIdx.x, lane = tid & 31, wid = tid >> 5;
    int gid = lane >> 2, tig = lane & 3;
    int wms = wid & 3, wns = wid >> 2;  // scores: rows wms*16, cols wns*8
    int wmz = wid & 1, wnz = wid >> 1;  // Z: rows wmz*32, cols wnz*64

    const float*    kvph = kvp + (long)h * T_SEQ * KVW;
    const uint32_t* khh = kbh + (long)h * T_SEQ * 32;
    const uint32_t* khl = kbl + (long)h * T_SEQ * 32;

    // K-tile loader indices
    int karr = tid >> 8, krr = (tid >> 3) & 31, kch = (tid & 7) * 4;
    const uint32_t* ksrcb = (karr ? khl : khh);
    uint32_t kdst_off = (karr ? OFF_KL : OFF_KH) + krr * 40 + kch;

    auto issue_tile = [&](int jt, int s) {
        // KV: 4096 contiguous 16B chunks, 8 per thread
        const float* src = kvph + (long)jt * 16384;
        uint32_t dstw = OFF_KV + s * KV_STG;
#pragma unroll
        for (int i = 0; i < 8; i++) {
            int idx = tid + i * 512;
            CP16(sbase + (dstw + idx * 4) * 4, src + idx * 4);
        }
        // K bf16 tiles: 512 chunks, 1 per thread
        CP16(sbase + (kdst_off + s * KH_STG) * 4,
             ksrcb + (long)(jt * TK + krr) * 32 + kch);
    };

    // prologue: Q tiles + tile 0
    {
        const uint32_t* qhh = qbh + ((long)h * T_SEQ + r0) * 32;
        const uint32_t* qhl = qbl + ((long)h * T_SEQ + r0) * 32;
#pragma unroll
        for (int i = 0; i < 2; i++) {
            int idx = tid + i * 512;
            int arr = idx >> 9, rr = (idx >> 3) & 63, ch = (idx & 7) * 4;
            const uint32_t* src = (arr ? qhl : qhh) + (long)rr * 32 + ch;
            uint32_t dst = sbase + ((arr ? OFF_QL : OFF_QH) + rr * 40 + ch) * 4;
            CP16(dst, src);
        }
        issue_tile(0, 0);
        CP_COMMIT();
    }

    float zacc[2][8][4];
#pragma unroll
    for (int i = 0; i < 2; i++)
#pragma unroll
        for (int j = 0; j < 8; j++)
#pragma unroll
            for (int q = 0; q < 4; q++) zacc[i][j][q] = 0.f;
    float s_acc0 = 0.f, s_acc1 = 0.f;

    int rowa = wms * 16 + gid;
    // physical P columns for this lane's logical cols 2tig, 2tig+1
    int phys0 = ((2 * tig) & 3) * 2 + (tig >> 1);
    int phys1 = ((2 * tig + 1) & 3) * 2 + (tig >> 1);

    for (int jt = 0; jt < njt; jt++) {
        int s = jt & 1;
        if (jt + 1 < njt) {
            issue_tile(jt + 1, s ^ 1);
            CP_COMMIT();
            asm volatile("cp.async.wait_group 1;" ::: "memory");
        } else {
            asm volatile("cp.async.wait_group 0;" ::: "memory");
        }
        __syncthreads();

        // ---- scores (3 independent acc chains) ----
        float sc3[3][4];
#pragma unroll
        for (int p = 0; p < 3; p++)
#pragma unroll
            for (int q = 0; q < 4; q++) sc3[p][q] = 0.f;
#pragma unroll
        for (int ks = 0; ks < 4; ks++) {
#pragma unroll
            for (int p = 0; p < 3; p++) {
                const uint32_t* Ab = usm + (p == 2 ? OFF_QL : OFF_QH);
                const uint32_t* Bb = usm + (p == 1 ? OFF_KL : OFF_KH) + s * KH_STG;
                uint2 qa = *(const uint2*)(Ab + rowa * 40 + ks * 8 + 2 * tig);
                uint2 qb = *(const uint2*)(Ab + (rowa + 8) * 40 + ks * 8 + 2 * tig);
                uint2 kb = *(const uint2*)(Bb + (wns * 8 + gid) * 40 + ks * 8 + 2 * tig);
                mma_bf16(sc3[p], qa.x, qb.x, qa.y, qb.y, kb.x, kb.y);
            }
        }
        float s0 = sc3[0][0] + sc3[1][0] + sc3[2][0];
        float s1 = sc3[0][1] + sc3[1][1] + sc3[2][1];
        float s2 = sc3[0][2] + sc3[1][2] + sc3[2][2];
        float s3 = sc3[0][3] + sc3[1][3] + sc3[2][3];

        // ---- exp + causal mask + permuted tf32 P store + reg row-sums ----
        {
            int colg = jt * TK + wns * 8 + tig * 2;
            float p00 = __expf(s0 * 0.125f);
            float p01 = __expf(s1 * 0.125f);
            float p10 = __expf(s2 * 0.125f);
            float p11 = __expf(s3 * 0.125f);
            if (jt >= njt - 2) {
                if (colg     > r0 + rowa)     p00 = 0.f;
                if (colg + 1 > r0 + rowa)     p01 = 0.f;
                if (colg     > r0 + rowa + 8) p10 = 0.f;
                if (colg + 1 > r0 + rowa + 8) p11 = 0.f;
            }
            p00 = tf32r(p00); p01 = tf32r(p01);
            p10 = tf32r(p10); p11 = tf32r(p11);
            float* Pr = fsm + OFF_P + rowa * 40 + wns * 8;
            Pr[phys0] = p00; Pr[phys1] = p01;
            Pr[8 * 40 + phys0] = p10; Pr[8 * 40 + phys1] = p11;
            s_acc0 += p00 + p01;
            s_acc1 += p10 + p11;
        }
        __syncthreads();

        // ---- Z += P @ KV (tf32, LDS.64 frags) ----
        {
            const float* KVs = fsm + OFF_KV + s * KV_STG;
#pragma unroll
            for (int ks = 0; ks < 4; ks++) {
                uint2 pa[2][2];
#pragma unroll
                for (int mt = 0; mt < 2; mt++) {
                    const float* Pr = fsm + OFF_P +
                        (wmz * 32 + mt * 16 + gid) * 40 + ks * 8 + 2 * tig;
                    pa[mt][0] = *(const uint2*)Pr;
                    pa[mt][1] = *(const uint2*)(Pr + 8 * 40);
                }
#pragma unroll
                for (int nt = 0; nt < 8; nt++) {
                    int c = wnz * 64 + nt * 8 + gid;
                    uint2 bb = *(const uint2*)(KVs + (ks * 512 + c) * 8 + 2 * tig);
                    mma_tf32(zacc[0][nt], pa[0][0].x, pa[0][1].x,
                             pa[0][0].y, pa[0][1].y, bb.x, bb.y);
                    mma_tf32(zacc[1][nt], pa[1][0].x, pa[1][1].x,
                             pa[1][0].y, pa[1][1].y, bb.x, bb.y);
                }
            }
        }
        __syncthreads();
    }

    // ---- Z regs -> smem, de-conflicted layout col' = c + (c>>6) ----
#pragma unroll
    for (int mt = 0; mt < 2; mt++) {
        int row = wmz * 32 + mt * 16 + gid;
#pragma unroll
        for (int nt = 0; nt < 8; nt++) {
            int c = wnz * 64 + nt * 8 + tig * 2;
            float* zp = fsm + OFF_KV + row * 520 + c + wnz;
            zp[0] = zacc[mt][nt][0];
            zp[1] = zacc[mt][nt][1];
            zp[8 * 520] = zacc[mt][nt][2];
            zp[8 * 520 + 1] = zacc[mt][nt][3];
        }
    }
    // ---- S: quad-reduce over tig, partials per wns ----
    s_acc0 += __shfl_xor_sync(~0u, s_acc0, 1);
    s_acc0 += __shfl_xor_sync(~0u, s_acc0, 2);
    s_acc1 += __shfl_xor_sync(~0u, s_acc1, 1);
    s_acc1 += __shfl_xor_sync(~0u, s_acc1, 2);
    if (tig == 0) {
        fsm[OFF_S + wns * 64 + rowa] = s_acc0;
        fsm[OFF_S + wns * 64 + rowa + 8] = s_acc1;
    }
    __syncthreads();
    if (tid < 64) {
        float sum = fsm[OFF_S + tid] + fsm[OFF_S + 64 + tid] +
                    fsm[OFF_S + 128 + tid] + fsm[OFF_S + 192 + tid];
        fsm[OFF_S + tid] = 1.f / sum;
    }
    __syncthreads();

    // ---- octonion epilogue (conflict-free scalar z reads) ----
    {
        int row = tid >> 3, m = tid & 7;
        float invS = fsm[OFF_S + row];
        const float* q = qn + ((long)h * T_SEQ + r0 + row) * HD + m * 8;
        const float* z = fsm + OFF_KV + row * 520 + m * 65;

        float q8[8];
        float4 qa = *(const float4*)q, qb = *(const float4*)(q + 4);
        q8[0]=qa.x; q8[1]=qa.y; q8[2]=qa.z; q8[3]=qa.w;
        q8[4]=qb.x; q8[5]=qb.y; q8[6]=qb.z; q8[7]=qb.w;
        float acc[8] = {0,0,0,0,0,0,0,0};
#pragma unroll
        for (int p = 0; p < 8; p++) {
            float e[8] = {0,0,0,0,0,0,0,0};
            e[p] = 1.f;
            float uo[8], z8[8], wv[8];
            omul8(q8, e, uo);   // folds to signed permutation
#pragma unroll
            for (int i = 0; i < 8; i++) z8[i] = z[p * 8 + i];
            omul8(uo, z8, wv);
#pragma unroll
            for (int k = 0; k < 8; k++) acc[k] += wv[k];
        }
        float* yo = y + (long)(r0 + row) * CEMB + h * HD + m * 8;
        *(float4*)yo = make_float4(acc[0]*invS, acc[1]*invS, acc[2]*invS, acc[3]*invS);
        *(float4*)(yo + 4) = make_float4(acc[4]*invS, acc[5]*invS, acc[6]*invS, acc[7]*invS);
    }
}

// ---------------- launch -----------------------------------------------------
extern "C" void kernel_launch(void* const* d_in, const int* in_sizes, int n_in,
                              void* d_out, int out_size)
{
    const float* x    = (const float*)d_in[0];
    const float* cosp = (const float*)d_in[1];
    const float* sinp = (const float*)d_in[2];
    const float* Wq   = (const float*)d_in[3];
    const float* Wk   = (const float*)d_in[4];
    const float* Wv   = (const float*)d_in[5];
    const float* Wo   = (const float*)d_in[6];
    float* out = (float*)d_out;

    float *qraw, *kraw, *vraw, *qn, *kvp, *y;
    uint32_t *qbh, *qbl, *kbh, *kbl;
    cudaGetSymbolAddress((void**)&qraw, g_qraw);
    cudaGetSymbolAddress((void**)&kraw, g_kraw);
    cudaGetSymbolAddress((void**)&vraw, g_vraw);
    cudaGetSymbolAddress((void**)&qn,   g_qn);
    cudaGetSymbolAddress((void**)&kvp,  g_kvp);
    cudaGetSymbolAddress((void**)&qbh,  g_qbh);
    cudaGetSymbolAddress((void**)&qbl,  g_qbl);
    cudaGetSymbolAddress((void**)&kbh,  g_kbh);
    cudaGetSymbolAddress((void**)&kbl,  g_kbl);
    cudaGetSymbolAddress((void**)&y,    g_y);

    const int smem_bf16 = 2 * 4 * BTILE_U * 4;   // 49152 B
    cudaFuncSetAttribute(qkv_gemm, cudaFuncAttributeMaxDynamicSharedMemorySize, smem_bf16);
    cudaFuncSetAttribute(wo_gemm,  cudaFuncAttributeMaxDynamicSharedMemorySize, smem_bf16);
    cudaFuncSetAttribute(fused_attn, cudaFuncAttributeMaxDynamicSharedMemorySize, FA_SMEM);

    // 1) merged QKV projections (3xBF16 split, NT)
    qkv_gemm<<<dim3(CEMB / 128, T_SEQ / 128, 3), 256, smem_bf16>>>(
        x, Wq, Wk, Wv, qraw, kraw, vraw);

    // 2) rotary + rms + octet-norm + paired tf32 KV + permuted bf16 packing
    prep_kernel<<<dim3(NH, T_SEQ / 8), 512>>>(qraw, kraw, vraw, cosp, sinp,
                                              qn, kvp, qbh, qbl, kbh, kbl);

    // 3) fused scores+softmax+Z+octonion-epilogue -> y
    fused_attn<<<dim3(32, NH), 512, FA_SMEM>>>(qn, qbh, qbl, kbh, kbl, kvp, y);

    // 4) out = y @ Wo^T (3xBF16 split)
    wo_gemm<<<dim3(CEMB / 128, T_SEQ / 128), 256, smem_bf16>>>(y, Wo, out);
}

// round 8
// speedup vs baseline: 1.5672x; 1.0050x over previous
#include <cuda_runtime.h>
#include <cstdint>
#include <math.h>

#define T_SEQ 2048
#define NH 16
#define HD 64
#define CEMB 1024
#define KVW 512

// ---------------- scratch (device globals) ----------------------------------
static __device__ float g_qraw[T_SEQ * CEMB];
static __device__ float g_kraw[T_SEQ * CEMB];
static __device__ float g_vraw[T_SEQ * CEMB];
static __device__ float g_qn[NH * T_SEQ * HD];
static __device__ float g_kvp[NH * T_SEQ * KVW];        // paired layout [h][g][c][w']
static __device__ uint32_t g_qbh[NH * T_SEQ * 32];      // q bf16-hi packed (permuted words)
static __device__ uint32_t g_qbl[NH * T_SEQ * 32];
static __device__ uint32_t g_kbh[NH * T_SEQ * 32];
static __device__ uint32_t g_kbl[NH * T_SEQ * 32];
static __device__ float g_y[T_SEQ * CEMB];

// ---------------- helpers ----------------------------------------------------
static __device__ __forceinline__ uint32_t smem_u32(const void* p) {
    uint32_t a;
    asm("{ .reg .u64 t; cvta.to.shared.u64 t, %1; cvt.u32.u64 %0, t; }" : "=r"(a) : "l"(p));
    return a;
}
static __device__ __forceinline__ float tf32r(float x) {
    float y; asm("cvt.rna.tf32.f32 %0, %1;" : "=f"(y) : "f"(x)); return y;
}
static __device__ __forceinline__ void mma_tf32(
    float* acc, uint32_t a0, uint32_t a1, uint32_t a2, uint32_t a3,
    uint32_t b0, uint32_t b1)
{
    asm volatile(
        "mma.sync.aligned.m16n8k8.row.col.f32.tf32.tf32.f32 "
        "{%0,%1,%2,%3},{%4,%5,%6,%7},{%8,%9},{%0,%1,%2,%3};"
        : "+f"(acc[0]), "+f"(acc[1]), "+f"(acc[2]), "+f"(acc[3])
        : "r"(a0), "r"(a1), "r"(a2), "r"(a3), "r"(b0), "r"(b1));
}
static __device__ __forceinline__ void mma_bf16(
    float* acc, uint32_t a0, uint32_t a1, uint32_t a2, uint32_t a3,
    uint32_t b0, uint32_t b1)
{
    asm volatile(
        "mma.sync.aligned.m16n8k16.row.col.f32.bf16.bf16.f32 "
        "{%0,%1,%2,%3},{%4,%5,%6,%7},{%8,%9},{%0,%1,%2,%3};"
        : "+f"(acc[0]), "+f"(acc[1]), "+f"(acc[2]), "+f"(acc[3])
        : "r"(a0), "r"(a1), "r"(a2), "r"(a3), "r"(b0), "r"(b1));
}
static __device__ __forceinline__ uint2 pack_split(float f0, float f1) {
    uint32_t h;
    asm("cvt.rn.bf16x2.f32 %0, %1, %2;" : "=r"(h) : "f"(f1), "f"(f0));
    float h0 = __uint_as_float(h << 16);
    float h1 = __uint_as_float(h & 0xffff0000u);
    uint32_t l;
    float r0 = f0 - h0, r1 = f1 - h1;
    asm("cvt.rn.bf16x2.f32 %0, %1, %2;" : "=r"(l) : "f"(r1), "f"(r0));
    return make_uint2(h, l);
}
#define CP16(dst_u32, src_ptr) \
    asm volatile("cp.async.cg.shared.global [%0], [%1], 16;" \
                 :: "r"(dst_u32), "l"(src_ptr) : "memory")
#define CP_COMMIT() asm volatile("cp.async.commit_group;" ::: "memory")

static __device__ __forceinline__ int permw(int d) {
    return (d & ~7) + ((d & 3) * 2 + ((d & 7) >> 2));
}

// ================= bf16 3x-split GEMM (NT), 128x64 tiles =====================
#define BSTR 12
#define GA_HI 0
#define GB_HI (128 * BSTR)
#define GA_LO (GB_HI + 64 * BSTR)
#define GB_LO (GA_LO + 128 * BSTR)
#define GSTAGE (GB_LO + 64 * BSTR)      // 3840 words per stage

static __device__ __forceinline__ void bf16_nt_body(
    const float* __restrict__ A, const float* __restrict__ B, float* __restrict__ C,
    int K, int lda, int ldb, int ldc, int m0, int n0)
{
    extern __shared__ uint32_t smu[];
    int nch = K >> 4;

    int tid = threadIdx.x;
    int lane = tid & 31, wid = tid >> 5;
    int gid = lane >> 2, tig = lane & 3;
    int warp_m = wid & 3, warp_n = wid >> 2;
    int arow = tid >> 1, akc = (tid & 1) * 8;
    int brow = tid >> 2, bkc = (tid & 3) * 4;

    float acc[2][4][4];
#pragma unroll
    for (int i = 0; i < 2; i++)
#pragma unroll
        for (int j = 0; j < 4; j++)
#pragma unroll
            for (int q = 0; q < 4; q++) acc[i][j][q] = 0.f;

    float4 ra0, ra1, rb0;
    auto LOADG = [&](int k0) {
        const float* ap = A + (long)(m0 + arow) * lda + k0 + akc;
        ra0 = *(const float4*)ap;
        ra1 = *(const float4*)(ap + 4);
        rb0 = *(const float4*)(B + (long)(n0 + brow) * ldb + k0 + bkc);
    };
    auto STORES = [&](int sb) {
        int ao = arow * BSTR + (akc >> 1);
        uint2 p0 = pack_split(ra0.x, ra0.y), p1 = pack_split(ra0.z, ra0.w);
        uint2 p2 = pack_split(ra1.x, ra1.y), p3 = pack_split(ra1.z, ra1.w);
        *(uint4*)(smu + sb + GA_HI + ao) = make_uint4(p0.x, p1.x, p2.x, p3.x);
        *(uint4*)(smu + sb + GA_LO + ao) = make_uint4(p0.y, p1.y, p2.y, p3.y);
        uint2 q0 = pack_split(rb0.x, rb0.y), q1 = pack_split(rb0.z, rb0.w);
        int bo = brow * BSTR + (bkc >> 1);
        *(uint2*)(smu + sb + GB_HI + bo) = make_uint2(q0.x, q1.x);
        *(uint2*)(smu + sb + GB_LO + bo) = make_uint2(q0.y, q1.y);
    };

    LOADG(0);
    STORES(0);
    __syncthreads();

    for (int ch = 0; ch < nch; ch++) {
        if (ch + 1 < nch) LOADG((ch + 1) << 4);
        int sb = (ch & 1) * GSTAGE;
#pragma unroll
        for (int p = 0; p < 3; p++) {
            const uint32_t* Abase = smu + sb + (p == 2 ? GA_LO : GA_HI);
            const uint32_t* Bbase = smu + sb + (p == 1 ? GB_LO : GB_HI);
            uint32_t af[2][4];
#pragma unroll
            for (int mt = 0; mt < 2; mt++) {
                int r = (warp_m * 32 + mt * 16 + gid) * BSTR + tig;
                af[mt][0] = Abase[r];
                af[mt][1] = Abase[r + 8 * BSTR];
                af[mt][2] = Abase[r + 4];
                af[mt][3] = Abase[r + 8 * BSTR + 4];
            }
            uint32_t bfr[4][2];
#pragma unroll
            for (int nt = 0; nt < 4; nt++) {
                int c = (warp_n * 32 + nt * 8 + gid) * BSTR + tig;
                bfr[nt][0] = Bbase[c];
                bfr[nt][1] = Bbase[c + 4];
            }
#pragma unroll
            for (int mt = 0; mt < 2; mt++)
#pragma unroll
                for (int nt = 0; nt < 4; nt++)
                    mma_bf16(acc[mt][nt], af[mt][0], af[mt][1], af[mt][2],
                             af[mt][3], bfr[nt][0], bfr[nt][1]);
        }
        if (ch + 1 < nch) {
            __syncthreads();
            STORES(((ch + 1) & 1) * GSTAGE);
            __syncthreads();
        }
    }

#pragma unroll
    for (int mt = 0; mt < 2; mt++) {
        int r0 = m0 + warp_m * 32 + mt * 16 + gid;
#pragma unroll
        for (int nt = 0; nt < 4; nt++) {
            int c = n0 + warp_n * 32 + nt * 8 + tig * 2;
            *(float2*)(C + (long)r0 * ldc + c) =
                make_float2(acc[mt][nt][0], acc[mt][nt][1]);
            *(float2*)(C + (long)(r0 + 8) * ldc + c) =
                make_float2(acc[mt][nt][2], acc[mt][nt][3]);
        }
    }
}

__global__ void __launch_bounds__(256, 2) qkv_gemm(
    const float* __restrict__ x,
    const float* __restrict__ Wq, const float* __restrict__ Wk,
    const float* __restrict__ Wv,
    float* q, float* k, float* v)
{
    const float* B = blockIdx.z == 0 ? Wq : blockIdx.z == 1 ? Wk : Wv;
    float* C = blockIdx.z == 0 ? q : blockIdx.z == 1 ? k : v;
    bf16_nt_body(x, B, C, CEMB, CEMB, CEMB, CEMB,
                 blockIdx.y * 128, blockIdx.x * 64);
}

__global__ void __launch_bounds__(256, 2) wo_gemm(
    const float* __restrict__ y, const float* __restrict__ Wo, float* out)
{
    bf16_nt_body(y, Wo, out, CEMB, CEMB, CEMB, CEMB,
                 blockIdx.y * 128, blockIdx.x * 64);
}

// ---------------- prep (unchanged from R7) -----------------------------------
__global__ __launch_bounds__(512) void prep_kernel(
    const float* __restrict__ qraw, const float* __restrict__ kraw,
    const float* __restrict__ vraw,
    const float* __restrict__ cosp, const float* __restrict__ sinp,
    float* __restrict__ qn, float* __restrict__ kvp,
    uint32_t* __restrict__ qbh, uint32_t* __restrict__ qbl,
    uint32_t* __restrict__ kbh, uint32_t* __restrict__ kbl)
{
    int h = blockIdx.x, g = blockIdx.y;
    int tid = threadIdx.x;
    int w = tid >> 6, d = tid & 63;
    int t = g * 8 + w;

    __shared__ float r1[8][64], r2[8][64], skc[8][64], sv[8][64];
    __shared__ float sq[8][64], sk[8][64];
    __shared__ float kvstage[8][512];

    long base = (long)t * CEMB + h * HD;
    int j = d & 31;
    float c = cosp[t * 32 + j], s = sinp[t * 32 + j];

    float x1q = qraw[base + j], x2q = qraw[base + j + 32];
    float qv = (d < 32) ? (x1q * c + x2q * s) : (x2q * c - x1q * s);
    float x1k = kraw[base + j], x2k = kraw[base + j + 32];
    float kvv = (d < 32) ? (x1k * c + x2k * s) : (x2k * c - x1k * s);

    r1[w][d] = qv * qv;
    r2[w][d] = kvv * kvv;
    __syncthreads();
#pragma unroll
    for (int off = 32; off > 0; off >>= 1) {
        if (d < off) { r1[w][d] += r1[w][d + off]; r2[w][d] += r2[w][d + off]; }
        __syncthreads();
    }
    float rq = rsqrtf(r1[w][0] * (1.f / 64.f) + 1e-6f);
    float rk = rsqrtf(r2[w][0] * (1.f / 64.f) + 1e-6f);
    float qno = qv * rq, kno = kvv * rk;

    qn[((long)h * T_SEQ + t) * HD + d] = qno;
    sq[w][d] = qno;
    sk[w][d] = kno;

    float o = kno * kno;
    o += __shfl_xor_sync(0xffffffffu, o, 1);
    o += __shfl_xor_sync(0xffffffffu, o, 2);
    o += __shfl_xor_sync(0xffffffffu, o, 4);
    float ko = kno / fmaxf(sqrtf(o), 1e-12f);
    skc[w][d] = ((d & 7) == 0) ? ko : -ko;
    sv[w][d] = vraw[base + d];
    __syncthreads();

    {
        float kc = skc[w][d];
        int mb = d & ~7;
#pragma unroll
        for (int i = 0; i < 8; i++)
            kvstage[w][d * 8 + i] = tf32r(kc * sv[w][mb + i]);
    }
    {
        long pbase = ((long)h * T_SEQ + t) * 32;
        if (d < 32) {
            uint2 p = pack_split(sq[w][2 * d], sq[w][2 * d + 1]);
            qbh[pbase + permw(d)] = p.x;
            qbl[pbase + permw(d)] = p.y;
        } else {
            int d2 = d - 32;
            uint2 p = pack_split(sk[w][2 * d2], sk[w][2 * d2 + 1]);
            kbh[pbase + permw(d2)] = p.x;
            kbl[pbase + permw(d2)] = p.y;
        }
    }
    __syncthreads();

    float* outb = kvp + ((long)(h * 256 + g) * 512) * 8;
#pragma unroll
    for (int it = 0; it < 2; it++) {
        int idx = tid + it * 512;
        int cc = idx >> 1, half = idx & 1;
        float4 v;
        v.x = kvstage[((half * 4 + 0) >> 1) + ((half * 4 + 0) & 1) * 4][cc];
        v.y = kvstage[((half * 4 + 1) >> 1) + ((half * 4 + 1) & 1) * 4][cc];
        v.z = kvstage[((half * 4 + 2) >> 1) + ((half * 4 + 2) & 1) * 4][cc];
        v.w = kvstage[((half * 4 + 3) >> 1) + ((half * 4 + 3) & 1) * 4][cc];
        *(float4*)(outb + cc * 8 + half * 4) = v;
    }
}

// ---------------- octonion math ----------------------------------------------
__device__ __forceinline__ void qmul4(const float* q1, const float* q2, float* r)
{
    r[0] = q1[0]*q2[0] - q1[1]*q2[1] - q1[2]*q2[2] - q1[3]*q2[3];
    r[1] = q1[0]*q2[1] + q1[1]*q2[0] + q1[2]*q2[3] - q1[3]*q2[2];
    r[2] = q1[0]*q2[2] - q1[1]*q2[3] + q1[2]*q2[0] + q1[3]*q2[1];
    r[3] = q1[0]*q2[3] + q1[1]*q2[2] - q1[2]*q2[1] + q1[3]*q2[0];
}
__device__ __forceinline__ void omul8(const float* o1, const float* o2, float* r)
{
    const float* a = o1; const float* b = o1 + 4;
    const float* c = o2; const float* d = o2 + 4;
    float dc[4] = { d[0], -d[1], -d[2], -d[3] };
    float cc[4] = { c[0], -c[1], -c[2], -c[3] };
    float t1[4], t2[4];
    qmul4(a, c, t1); qmul4(dc, b, t2);
    r[0] = t1[0] - t2[0]; r[1] = t1[1] - t2[1];
    r[2] = t1[2] - t2[2]; r[3] = t1[3] - t2[3];
    qmul4(d, a, t1); qmul4(b, cc, t2);
    r[4] = t1[0] + t2[0]; r[5] = t1[1] + t2[1];
    r[6] = t1[2] + t2[2]; r[7] = t1[3] + t2[3];
}

// ================= fused attention: 256 thr, Z read-once, Q in regs ==========
#define TK 32
// word offsets in dynamic smem
#define OFF_KV 0
#define KV_STG 16384            // 4 kgroups * 512c * 8
#define OFF_KH 32768            // 2 stages x 32x40
#define KH_STG 1280
#define OFF_KL 35328
#define OFF_P  37888            // 64 x 40
#define OFF_QH 40448            // 64 x 40
#define OFF_QL 43008
#define OFF_S  45568            // 2 x 64 + 64
#define FA_SMEM ((OFF_S + 192) * 4)

__global__ void __launch_bounds__(256, 1) fused_attn(
    const float* __restrict__ qn,
    const uint32_t* __restrict__ qbh, const uint32_t* __restrict__ qbl,
    const uint32_t* __restrict__ kbh, const uint32_t* __restrict__ kbl,
    const float* __restrict__ kvp, float* __restrict__ y)
{
    extern __shared__ __align__(16) float fsm[];
    uint32_t* usm = (uint32_t*)fsm;
    uint32_t sbase = smem_u32(fsm);

    int qt = 31 - blockIdx.x;
    int h = blockIdx.y;
    int r0 = qt * 64;
    int njt = 2 * qt + 2;

    int tid = threadIdx.x, lane = tid & 31, wid = tid >> 5;
    int gid = lane >> 2, tig = lane & 3;
    int wms = wid & 3, wns = wid >> 2;   // scores: rows wms*16, keys wns*16

    const float*    kvph = kvp + (long)h * T_SEQ * KVW;
    const uint32_t* khh = kbh + (long)h * T_SEQ * 32;
    const uint32_t* khl = kbl + (long)h * T_SEQ * 32;

    // K-tile loader: 2 chunks/thread
    auto issue_tile = [&](int jt, int s) {
        const float* src = kvph + (long)jt * 16384;
        uint32_t dstw = OFF_KV + s * KV_STG;
#pragma unroll
        for (int i = 0; i < 16; i++) {
            int idx = tid + i * 256;
            CP16(sbase + (dstw + idx * 4) * 4, src + idx * 4);
        }
#pragma unroll
        for (int i = 0; i < 2; i++) {
            int idx = tid + i * 256;
            int arr = idx >> 8, rr = (idx >> 3) & 31, ch = (idx & 7) * 4;
            const uint32_t* sb2 = (arr ? khl : khh) + (long)(jt * TK + rr) * 32 + ch;
            CP16(sbase + ((arr ? OFF_KL : OFF_KH) + s * KH_STG + rr * 40 + ch) * 4, sb2);
        }
    };

    // prologue: Q tiles then tile 0
    {
        const uint32_t* qhh = qbh + ((long)h * T_SEQ + r0) * 32;
        const uint32_t* qhl = qbl + ((long)h * T_SEQ + r0) * 32;
#pragma unroll
        for (int i = 0; i < 4; i++) {
            int idx = tid + i * 256;
            int arr = idx >> 9, rr = (idx >> 3) & 63, ch = (idx & 7) * 4;
            const uint32_t* src = (arr ? qhl : qhh) + (long)rr * 32 + ch;
            CP16(sbase + ((arr ? OFF_QL : OFF_QH) + rr * 40 + ch) * 4, src);
        }
        CP_COMMIT();
        issue_tile(0, 0);
        CP_COMMIT();
        asm volatile("cp.async.wait_group 1;" ::: "memory");
        __syncthreads();
    }

    int rowa = wms * 16 + gid;
    // preload Q frags into registers (score rows of this warp)
    uint32_t qh[4][4], ql[4][4];
#pragma unroll
    for (int ks = 0; ks < 4; ks++) {
        int b = rowa * 40 + ks * 8 + 2 * tig;
        uint2 a = *(const uint2*)(usm + OFF_QH + b);
        uint2 bb = *(const uint2*)(usm + OFF_QH + b + 8 * 40);
        qh[ks][0] = a.x; qh[ks][1] = bb.x; qh[ks][2] = a.y; qh[ks][3] = bb.y;
        uint2 c = *(const uint2*)(usm + OFF_QL + b);
        uint2 d = *(const uint2*)(usm + OFF_QL + b + 8 * 40);
        ql[ks][0] = c.x; ql[ks][1] = d.x; ql[ks][2] = c.y; ql[ks][3] = d.y;
    }

    float zacc[4][8][4];
#pragma unroll
    for (int i = 0; i < 4; i++)
#pragma unroll
        for (int j = 0; j < 8; j++)
#pragma unroll
            for (int q = 0; q < 4; q++) zacc[i][j][q] = 0.f;
    float s_acc0 = 0.f, s_acc1 = 0.f;

    int phys0 = ((2 * tig) & 3) * 2 + (tig >> 1);
    int phys1 = ((2 * tig + 1) & 3) * 2 + (tig >> 1);

    for (int jt = 0; jt < njt; jt++) {
        int s = jt & 1;
        if (jt + 1 < njt) {
            issue_tile(jt + 1, s ^ 1);
            CP_COMMIT();
            asm volatile("cp.async.wait_group 1;" ::: "memory");
        } else {
            asm volatile("cp.async.wait_group 0;" ::: "memory");
        }
        __syncthreads();

        // ---- scores: warp tile 16 rows x 16 keys (2 n8 tiles) ----
#pragma unroll
        for (int nt = 0; nt < 2; nt++) {
            float sc3[3][4];
#pragma unroll
            for (int p = 0; p < 3; p++)
#pragma unroll
                for (int q = 0; q < 4; q++) sc3[p][q] = 0.f;
            int krow = (wns * 16 + nt * 8 + gid) * 40 + 2 * tig;
#pragma unroll
            for (int ks = 0; ks < 4; ks++) {
#pragma unroll
                for (int p = 0; p < 3; p++) {
                    const uint32_t* Aq = (p == 2) ? ql[ks] : qh[ks];
                    const uint32_t* Bb = usm + (p == 1 ? OFF_KL : OFF_KH) +
                                         s * KH_STG;
                    uint2 kb = *(const uint2*)(Bb + krow + ks * 8);
                    mma_bf16(sc3[p], Aq[0], Aq[1], Aq[2], Aq[3], kb.x, kb.y);
                }
            }
            float s0 = sc3[0][0] + sc3[1][0] + sc3[2][0];
            float s1 = sc3[0][1] + sc3[1][1] + sc3[2][1];
            float s2 = sc3[0][2] + sc3[1][2] + sc3[2][2];
            float s3 = sc3[0][3] + sc3[1][3] + sc3[2][3];

            int colg = jt * TK + wns * 16 + nt * 8 + tig * 2;
            float p00 = __expf(s0 * 0.125f);
            float p01 = __expf(s1 * 0.125f);
            float p10 = __expf(s2 * 0.125f);
            float p11 = __expf(s3 * 0.125f);
            if (jt >= njt - 2) {
                if (colg     > r0 + rowa)     p00 = 0.f;
                if (colg + 1 > r0 + rowa)     p01 = 0.f;
                if (colg     > r0 + rowa + 8) p10 = 0.f;
                if (colg + 1 > r0 + rowa + 8) p11 = 0.f;
            }
            p00 = tf32r(p00); p01 = tf32r(p01);
            p10 = tf32r(p10); p11 = tf32r(p11);
            float* Pr = fsm + OFF_P + rowa * 40 + wns * 16 + nt * 8;
            Pr[phys0] = p00; Pr[phys1] = p01;
            Pr[8 * 40 + phys0] = p10; Pr[8 * 40 + phys1] = p11;
            s_acc0 += p00 + p01;
            s_acc1 += p10 + p11;
        }
        __syncthreads();

        // ---- Z += P @ KV : warp tile 64 rows x 64 cols (KV read once) ----
        {
            const float* KVs = fsm + OFF_KV + s * KV_STG;
#pragma unroll
            for (int ks = 0; ks < 4; ks++) {
                uint2 pa[4][2];
#pragma unroll
                for (int mt = 0; mt < 4; mt++) {
                    const float* Pr = fsm + OFF_P +
                        (mt * 16 + gid) * 40 + ks * 8 + 2 * tig;
                    pa[mt][0] = *(const uint2*)Pr;
                    pa[mt][1] = *(const uint2*)(Pr + 8 * 40);
                }
#pragma unroll
                for (int nt = 0; nt < 8; nt++) {
                    int c = wid * 64 + nt * 8 + gid;
                    uint2 bb = *(const uint2*)(KVs + (ks * 512 + c) * 8 + 2 * tig);
#pragma unroll
                    for (int mt = 0; mt < 4; mt++)
                        mma_tf32(zacc[mt][nt], pa[mt][0].x, pa[mt][1].x,
                                 pa[mt][0].y, pa[mt][1].y, bb.x, bb.y);
                }
            }
        }
        __syncthreads();
    }

    // ---- S reduce: quad shuffle then 2 partials ----
    s_acc0 += __shfl_xor_sync(~0u, s_acc0, 1);
    s_acc0 += __shfl_xor_sync(~0u, s_acc0, 2);
    s_acc1 += __shfl_xor_sync(~0u, s_acc1, 1);
    s_acc1 += __shfl_xor_sync(~0u, s_acc1, 2);
    if (tig == 0) {
        fsm[OFF_S + wns * 64 + rowa] = s_acc0;
        fsm[OFF_S + wns * 64 + rowa + 8] = s_acc1;
    }
    // ---- Z regs -> smem (overlay on KV stages), stride 520, col'=c+wid ----
#pragma unroll
    for (int mt = 0; mt < 4; mt++) {
        int row = mt * 16 + gid;
#pragma unroll
        for (int nt = 0; nt < 8; nt++) {
            float* zp = fsm + row * 520 + wid * 65 + nt * 8 + tig * 2;
            zp[0] = zacc[mt][nt][0];
            zp[1] = zacc[mt][nt][1];
            zp[8 * 520] = zacc[mt][nt][2];
            zp[8 * 520 + 1] = zacc[mt][nt][3];
        }
    }
    __syncthreads();
    if (tid < 64)
        fsm[OFF_S + 128 + tid] = 1.f / (fsm[OFF_S + tid] + fsm[OFF_S + 64 + tid]);
    __syncthreads();

    // ---- octonion epilogue: 2 (row,m) units per thread ----
#pragma unroll
    for (int u2 = 0; u2 < 2; u2++) {
        int u = tid * 2 + u2;
        int row = u >> 3, m = u & 7;
        float invS = fsm[OFF_S + 128 + row];
        const float* q = qn + ((long)h * T_SEQ + r0 + row) * HD + m * 8;
        const float* z = fsm + row * 520 + m * 65;

        float q8[8];
        float4 qa = *(const float4*)q, qb = *(const float4*)(q + 4);
        q8[0]=qa.x; q8[1]=qa.y; q8[2]=qa.z; q8[3]=qa.w;
        q8[4]=qb.x; q8[5]=qb.y; q8[6]=qb.z; q8[7]=qb.w;
        float acc[8] = {0,0,0,0,0,0,0,0};
#pragma unroll
        for (int p = 0; p < 8; p++) {
            float e[8] = {0,0,0,0,0,0,0,0};
            e[p] = 1.f;
            float uo[8], z8[8], wv[8];
            omul8(q8, e, uo);
#pragma unroll
            for (int i = 0; i < 8; i++) z8[i] = z[p * 8 + i];
            omul8(uo, z8, wv);
#pragma unroll
            for (int k = 0; k < 8; k++) acc[k] += wv[k];
        }
        float* yo = y + (long)(r0 + row) * CEMB + h * HD + m * 8;
        *(float4*)yo = make_float4(acc[0]*invS, acc[1]*invS, acc[2]*invS, acc[3]*invS);
        *(float4*)(yo + 4) = make_float4(acc[4]*invS, acc[5]*invS, acc[6]*invS, acc[7]*invS);
    }
}

// ---------------- launch -----------------------------------------------------
extern "C" void kernel_launch(void* const* d_in, const int* in_sizes, int n_in,
                              void* d_out, int out_size)
{
    const float* x    = (const float*)d_in[0];
    const float* cosp = (const float*)d_in[1];
    const float* sinp = (const float*)d_in[2];
    const float* Wq   = (const float*)d_in[3];
    const float* Wk   = (const float*)d_in[4];
    const float* Wv   = (const float*)d_in[5];
    const float* Wo   = (const float*)d_in[6];
    float* out = (float*)d_out;

    float *qraw, *kraw, *vraw, *qn, *kvp, *y;
    uint32_t *qbh, *qbl, *kbh, *kbl;
    cudaGetSymbolAddress((void**)&qraw, g_qraw);
    cudaGetSymbolAddress((void**)&kraw, g_kraw);
    cudaGetSymbolAddress((void**)&vraw, g_vraw);
    cudaGetSymbolAddress((void**)&qn,   g_qn);
    cudaGetSymbolAddress((void**)&kvp,  g_kvp);
    cudaGetSymbolAddress((void**)&qbh,  g_qbh);
    cudaGetSymbolAddress((void**)&qbl,  g_qbl);
    cudaGetSymbolAddress((void**)&kbh,  g_kbh);
    cudaGetSymbolAddress((void**)&kbl,  g_kbl);
    cudaGetSymbolAddress((void**)&y,    g_y);

    const int smem_gemm = 2 * GSTAGE * 4;   // 30720 B
    cudaFuncSetAttribute(qkv_gemm, cudaFuncAttributeMaxDynamicSharedMemorySize, smem_gemm);
    cudaFuncSetAttribute(wo_gemm,  cudaFuncAttributeMaxDynamicSharedMemorySize, smem_gemm);
    cudaFuncSetAttribute(fused_attn, cudaFuncAttributeMaxDynamicSharedMemorySize, FA_SMEM);

    // 1) merged QKV projections (3xBF16 split, NT, 128x64 tiles)
    qkv_gemm<<<dim3(CEMB / 64, T_SEQ / 128, 3), 256, smem_gemm>>>(
        x, Wq, Wk, Wv, qraw, kraw, vraw);

    // 2) rotary + rms + octet-norm + paired tf32 KV + permuted bf16 packing
    prep_kernel<<<dim3(NH, T_SEQ / 8), 512>>>(qraw, kraw, vraw, cosp, sinp,
                                              qn, kvp, qbh, qbl, kbh, kbl);

    // 3) fused scores+softmax+Z+octonion-epilogue -> y
    fused_attn<<<dim3(32, NH), 256, FA_SMEM>>>(qn, qbh, qbl, kbh, kbl, kvp, y);

    // 4) out = y @ Wo^T (3xBF16 split, 128x64 tiles)
    wo_gemm<<<dim3(CEMB / 64, T_SEQ / 128), 256, smem_gemm>>>(y, Wo, out);
}